// round 1
// baseline (speedup 1.0000x reference)
#include <cuda_runtime.h>
#include <math.h>
#include <stdint.h>

#define N_NODES 50000
#define N_EDGES 1600000
#define IN_F    512
#define NH      128
#define NC      40

// ---------------- static scratch (no runtime allocation) ----------------
__device__ float g_deg_out[N_NODES];
__device__ float g_deg_in [N_NODES];
__device__ float g_ns     [N_NODES];              // rsqrt(max(deg_out,1))
__device__ float g_nd     [N_NODES];              // rsqrt(max(deg_in,1))
__device__ float g_h1     [(size_t)N_NODES * NH]; // (X@W1)*ns
__device__ float g_agg1   [(size_t)N_NODES * NH]; // scatter-add target L1
__device__ float g_h2     [(size_t)N_NODES * NC]; // (relu(agg1*nd+b1)@W2)*ns
__device__ float g_agg2   [(size_t)N_NODES * NC]; // scatter-add target L2

// ---------------- zero the accumulators each call ----------------
__global__ void zero_kernel() {
    int i = blockIdx.x * blockDim.x + threadIdx.x;
    int stride = gridDim.x * blockDim.x;
    for (int j = i; j < N_NODES; j += stride) { g_deg_out[j] = 0.f; g_deg_in[j] = 0.f; }
    float4 z = make_float4(0.f, 0.f, 0.f, 0.f);
    float4* a1 = reinterpret_cast<float4*>(g_agg1);
    for (int j = i; j < N_NODES * NH / 4; j += stride) a1[j] = z;
    float4* a2 = reinterpret_cast<float4*>(g_agg2);
    for (int j = i; j < N_NODES * NC / 4; j += stride) a2[j] = z;
}

// ---------------- degree histogram ----------------
__global__ void deg_kernel(const int* __restrict__ src, const int* __restrict__ dst) {
    int e = blockIdx.x * blockDim.x + threadIdx.x;
    if (e < N_EDGES) {
        atomicAdd(&g_deg_out[src[e]], 1.f);
        atomicAdd(&g_deg_in [dst[e]], 1.f);
    }
}

__global__ void norm_kernel() {
    int i = blockIdx.x * blockDim.x + threadIdx.x;
    if (i < N_NODES) {
        g_ns[i] = rsqrtf(fmaxf(g_deg_out[i], 1.f));
        g_nd[i] = rsqrtf(fmaxf(g_deg_in [i], 1.f));
    }
}

// ---------------- GEMM1: h1 = (X @ W1) * ns[row]  (M=50000,K=512,N=128) ----
// 128x128 block tile, BK=16, 256 threads, 8x8 per thread.
__global__ __launch_bounds__(256) void gemm1_kernel(const float* __restrict__ X,
                                                    const float* __restrict__ W1) {
    __shared__ float As[16][132];   // A transposed [k][m], padded
    __shared__ float Bs[16][132];   // [k][n]

    const int bm  = blockIdx.x * 128;
    const int tid = threadIdx.x;
    const int tx  = tid % 16;       // -> 8 output cols
    const int ty  = tid / 16;       // -> 8 output rows

    const int arow  = tid / 4;      // 0..63 ; rows arow, arow+64
    const int acol4 = tid % 4;      // float4 within 16 k-cols
    const int brow  = tid / 32;     // 0..7  ; rows brow, brow+8
    const int bcol  = (tid % 32) * 4;

    float acc[8][8];
    #pragma unroll
    for (int i = 0; i < 8; i++)
        #pragma unroll
        for (int j = 0; j < 8; j++) acc[i][j] = 0.f;

    for (int k0 = 0; k0 < IN_F; k0 += 16) {
        // load A tile (transpose into smem)
        #pragma unroll
        for (int r = 0; r < 2; r++) {
            int m   = arow + r * 64;
            int row = bm + m;
            float4 v = make_float4(0.f, 0.f, 0.f, 0.f);
            if (row < N_NODES)
                v = *reinterpret_cast<const float4*>(&X[(size_t)row * IN_F + k0 + acol4 * 4]);
            As[acol4 * 4 + 0][m] = v.x;
            As[acol4 * 4 + 1][m] = v.y;
            As[acol4 * 4 + 2][m] = v.z;
            As[acol4 * 4 + 3][m] = v.w;
        }
        // load B tile
        #pragma unroll
        for (int r = 0; r < 2; r++) {
            int kr = brow + r * 8;
            float4 v = *reinterpret_cast<const float4*>(&W1[(size_t)(k0 + kr) * NH + bcol]);
            *reinterpret_cast<float4*>(&Bs[kr][bcol]) = v;
        }
        __syncthreads();

        #pragma unroll
        for (int k = 0; k < 16; k++) {
            float am[8], bn[8];
            *reinterpret_cast<float4*>(&am[0]) = *reinterpret_cast<float4*>(&As[k][ty * 8]);
            *reinterpret_cast<float4*>(&am[4]) = *reinterpret_cast<float4*>(&As[k][ty * 8 + 4]);
            *reinterpret_cast<float4*>(&bn[0]) = *reinterpret_cast<float4*>(&Bs[k][tx * 8]);
            *reinterpret_cast<float4*>(&bn[4]) = *reinterpret_cast<float4*>(&Bs[k][tx * 8 + 4]);
            #pragma unroll
            for (int i = 0; i < 8; i++)
                #pragma unroll
                for (int j = 0; j < 8; j++)
                    acc[i][j] = fmaf(am[i], bn[j], acc[i][j]);
        }
        __syncthreads();
    }

    // epilogue: scale by norm_src and store
    #pragma unroll
    for (int i = 0; i < 8; i++) {
        int row = bm + ty * 8 + i;
        if (row < N_NODES) {
            float s = g_ns[row];
            #pragma unroll
            for (int j = 0; j < 8; j += 4) {
                float4 v = make_float4(acc[i][j] * s, acc[i][j + 1] * s,
                                       acc[i][j + 2] * s, acc[i][j + 3] * s);
                *reinterpret_cast<float4*>(&g_h1[(size_t)row * NH + tx * 8 + j]) = v;
            }
        }
    }
}

// ---------------- scatter 1: agg1[dst] += h1[src]  (128 feats, warp/edge) ---
__device__ __forceinline__ void red_add_v4(float* p, float4 v) {
    asm volatile("red.global.add.v4.f32 [%0], {%1,%2,%3,%4};"
                 :: "l"(p), "f"(v.x), "f"(v.y), "f"(v.z), "f"(v.w) : "memory");
}

__global__ void scatter1_kernel(const int* __restrict__ src, const int* __restrict__ dst) {
    int t = blockIdx.x * blockDim.x + threadIdx.x;
    int e = t >> 5;
    int lane = t & 31;
    if (e >= N_EDGES) return;
    int s = src[e];
    int d = dst[e];
    float4 v = __ldg(reinterpret_cast<const float4*>(&g_h1[(size_t)s * NH]) + lane);
    red_add_v4(&g_agg1[(size_t)d * NH + lane * 4], v);
}

// ---------------- GEMM2: h2 = (relu(agg1*nd + b1) @ W2) * ns  (K=128,N=40) --
__global__ __launch_bounds__(256) void gemm2_kernel(const float* __restrict__ b1,
                                                    const float* __restrict__ W2) {
    __shared__ float W2s[NH * NC];     // 5120 floats = 20KB
    __shared__ float xs[8][NH];        // 8 rows staged

    int tid = threadIdx.x;
    for (int i = tid; i < NH * NC; i += 256) W2s[i] = W2[i];
    __syncthreads();

    const int n_tiles = (N_NODES + 7) / 8;
    for (int tile = blockIdx.x; tile < n_tiles; tile += gridDim.x) {
        int row0 = tile * 8;
        // stage relu(agg1*nd + b1)
        #pragma unroll
        for (int i = 0; i < 4; i++) {
            int j = tid + i * 256;          // 0..1023
            int r = j >> 7, k = j & 127;
            int row = row0 + r;
            float val = 0.f;
            if (row < N_NODES)
                val = fmaxf(g_agg1[(size_t)row * NH + k] * g_nd[row] + b1[k], 0.f);
            xs[r][k] = val;
        }
        __syncthreads();

        for (int j = tid; j < 8 * NC; j += 256) {
            int r = j / NC, c = j % NC;
            int row = row0 + r;
            if (row < N_NODES) {
                float accv = 0.f;
                #pragma unroll 8
                for (int k = 0; k < NH; k++)
                    accv = fmaf(xs[r][k], W2s[k * NC + c], accv);
                g_h2[(size_t)row * NC + c] = accv * g_ns[row];
            }
        }
        __syncthreads();
    }
}

// ---------------- scatter 2: agg2[dst] += h2[src] (40 feats = 10 float4) ----
__global__ void scatter2_kernel(const int* __restrict__ src, const int* __restrict__ dst) {
    int t = blockIdx.x * blockDim.x + threadIdx.x;
    int e = t / 10;
    int c = t % 10;
    if (e >= N_EDGES) return;
    int s = src[e];
    int d = dst[e];
    float4 v = __ldg(reinterpret_cast<const float4*>(&g_h2[(size_t)s * NC + c * 4]));
    red_add_v4(&g_agg2[(size_t)d * NC + c * 4], v);
}

// ---------------- final: out = agg2*nd + b2 ----------------
__global__ void final_kernel(const float* __restrict__ b2, float* __restrict__ out) {
    int t = blockIdx.x * blockDim.x + threadIdx.x;
    if (t < N_NODES * NC) {
        int i = t / NC, c = t % NC;
        out[t] = g_agg2[t] * g_nd[i] + b2[c];
    }
}

// ---------------- launch ----------------
extern "C" void kernel_launch(void* const* d_in, const int* in_sizes, int n_in,
                              void* d_out, int out_size) {
    const float* X   = (const float*)d_in[0];
    const float* W1  = (const float*)d_in[1];
    const float* b1  = (const float*)d_in[2];
    const float* W2  = (const float*)d_in[3];
    const float* b2  = (const float*)d_in[4];
    const int*   src = (const int*)  d_in[5];
    const int*   dst = (const int*)  d_in[6];
    float* out = (float*)d_out;

    zero_kernel<<<2048, 256>>>();
    deg_kernel<<<(N_EDGES + 255) / 256, 256>>>(src, dst);
    norm_kernel<<<(N_NODES + 255) / 256, 256>>>();
    gemm1_kernel<<<(N_NODES + 127) / 128, 256>>>(X, W1);
    {
        long long threads = (long long)N_EDGES * 32;
        scatter1_kernel<<<(unsigned)((threads + 255) / 256), 256>>>(src, dst);
    }
    gemm2_kernel<<<2048, 256>>>(b1, W2);
    {
        long long threads = (long long)N_EDGES * 10;
        scatter2_kernel<<<(unsigned)((threads + 255) / 256), 256>>>(src, dst);
    }
    final_kernel<<<(N_NODES * NC + 255) / 256, 256>>>(b2, out);
}

// round 2
// speedup vs baseline: 1.1734x; 1.1734x over previous
#include <cuda_runtime.h>
#include <math.h>
#include <stdint.h>

#define N_NODES 50000
#define N_EDGES 1600000
#define IN_F    512
#define NH      128
#define NC      40

// ---------------- static scratch (no runtime allocation) ----------------
__device__ int   g_deg_out_i[N_NODES];
__device__ int   g_deg_in_i [N_NODES];
__device__ int   g_cursor   [N_NODES];
__device__ int   g_row_ptr  [N_NODES + 1];
__device__ int   g_eid_src  [N_EDGES];            // src node of each edge, grouped by dst
__device__ float g_ns       [N_NODES];            // rsqrt(max(deg_out,1))
__device__ float g_nd       [N_NODES];            // rsqrt(max(deg_in,1))
__device__ float g_h1       [(size_t)N_NODES * NH]; // (X@W1)*ns
__device__ float g_x2       [(size_t)N_NODES * NH]; // relu(agg1*nd + b1)
__device__ float g_h2       [(size_t)N_NODES * NC]; // (x2@W2)*ns

// ---------------- zero counters each call ----------------
__global__ void zero_kernel() {
    int i = blockIdx.x * blockDim.x + threadIdx.x;
    int stride = gridDim.x * blockDim.x;
    for (int j = i; j < N_NODES; j += stride) {
        g_deg_out_i[j] = 0;
        g_deg_in_i [j] = 0;
        g_cursor   [j] = 0;
    }
}

// ---------------- degree histogram (int atomics) ----------------
__global__ void deg_kernel(const int* __restrict__ src, const int* __restrict__ dst) {
    int e = blockIdx.x * blockDim.x + threadIdx.x;
    if (e < N_EDGES) {
        atomicAdd(&g_deg_out_i[src[e]], 1);
        atomicAdd(&g_deg_in_i [dst[e]], 1);
    }
}

__global__ void norm_kernel() {
    int i = blockIdx.x * blockDim.x + threadIdx.x;
    if (i < N_NODES) {
        g_ns[i] = rsqrtf(fmaxf((float)g_deg_out_i[i], 1.f));
        g_nd[i] = rsqrtf(fmaxf((float)g_deg_in_i [i], 1.f));
    }
}

// ---------------- exclusive prefix sum of deg_in -> row_ptr (1 block) ------
__global__ __launch_bounds__(1024) void scan_kernel() {
    __shared__ int sums[1024];
    const int t = threadIdx.x;
    const int CHUNK = (N_NODES + 1023) / 1024;   // 49
    int lo = t * CHUNK;
    int hi = lo + CHUNK; if (hi > N_NODES) hi = N_NODES;
    int s = 0;
    for (int i = lo; i < hi; i++) s += g_deg_in_i[i];
    sums[t] = s;
    __syncthreads();
    // Hillis-Steele inclusive scan over 1024 partials
    for (int off = 1; off < 1024; off <<= 1) {
        int v = (t >= off) ? sums[t - off] : 0;
        __syncthreads();
        sums[t] += v;
        __syncthreads();
    }
    int base = (t == 0) ? 0 : sums[t - 1];
    for (int i = lo; i < hi; i++) {
        g_row_ptr[i] = base;
        base += g_deg_in_i[i];
    }
    if (t == 1023) g_row_ptr[N_NODES] = base;
}

// ---------------- bucket edges by dst ----------------
__global__ void fill_kernel(const int* __restrict__ src, const int* __restrict__ dst) {
    int e = blockIdx.x * blockDim.x + threadIdx.x;
    if (e < N_EDGES) {
        int d = dst[e];
        int pos = g_row_ptr[d] + atomicAdd(&g_cursor[d], 1);
        g_eid_src[pos] = src[e];
    }
}

// ---------------- GEMM1: h1 = (X @ W1) * ns[row]  (M=50000,K=512,N=128) ----
__global__ __launch_bounds__(256) void gemm1_kernel(const float* __restrict__ X,
                                                    const float* __restrict__ W1) {
    __shared__ float As[16][132];   // A transposed [k][m], padded
    __shared__ float Bs[16][132];   // [k][n]

    const int bm  = blockIdx.x * 128;
    const int tid = threadIdx.x;
    const int tx  = tid % 16;
    const int ty  = tid / 16;

    const int arow  = tid / 4;
    const int acol4 = tid % 4;
    const int brow  = tid / 32;
    const int bcol  = (tid % 32) * 4;

    float acc[8][8];
    #pragma unroll
    for (int i = 0; i < 8; i++)
        #pragma unroll
        for (int j = 0; j < 8; j++) acc[i][j] = 0.f;

    for (int k0 = 0; k0 < IN_F; k0 += 16) {
        #pragma unroll
        for (int r = 0; r < 2; r++) {
            int m   = arow + r * 64;
            int row = bm + m;
            float4 v = make_float4(0.f, 0.f, 0.f, 0.f);
            if (row < N_NODES)
                v = *reinterpret_cast<const float4*>(&X[(size_t)row * IN_F + k0 + acol4 * 4]);
            As[acol4 * 4 + 0][m] = v.x;
            As[acol4 * 4 + 1][m] = v.y;
            As[acol4 * 4 + 2][m] = v.z;
            As[acol4 * 4 + 3][m] = v.w;
        }
        #pragma unroll
        for (int r = 0; r < 2; r++) {
            int kr = brow + r * 8;
            float4 v = *reinterpret_cast<const float4*>(&W1[(size_t)(k0 + kr) * NH + bcol]);
            *reinterpret_cast<float4*>(&Bs[kr][bcol]) = v;
        }
        __syncthreads();

        #pragma unroll
        for (int k = 0; k < 16; k++) {
            float am[8], bn[8];
            *reinterpret_cast<float4*>(&am[0]) = *reinterpret_cast<float4*>(&As[k][ty * 8]);
            *reinterpret_cast<float4*>(&am[4]) = *reinterpret_cast<float4*>(&As[k][ty * 8 + 4]);
            *reinterpret_cast<float4*>(&bn[0]) = *reinterpret_cast<float4*>(&Bs[k][tx * 8]);
            *reinterpret_cast<float4*>(&bn[4]) = *reinterpret_cast<float4*>(&Bs[k][tx * 8 + 4]);
            #pragma unroll
            for (int i = 0; i < 8; i++)
                #pragma unroll
                for (int j = 0; j < 8; j++)
                    acc[i][j] = fmaf(am[i], bn[j], acc[i][j]);
        }
        __syncthreads();
    }

    #pragma unroll
    for (int i = 0; i < 8; i++) {
        int row = bm + ty * 8 + i;
        if (row < N_NODES) {
            float s = g_ns[row];
            #pragma unroll
            for (int j = 0; j < 8; j += 4) {
                float4 v = make_float4(acc[i][j] * s, acc[i][j + 1] * s,
                                       acc[i][j + 2] * s, acc[i][j + 3] * s);
                *reinterpret_cast<float4*>(&g_h1[(size_t)row * NH + tx * 8 + j]) = v;
            }
        }
    }
}

// ---------------- agg1: x2[n] = relu(nd[n]*sum_{e->n} h1[src_e] + b1) -------
// warp per node; lane l owns float4 at feature offset 4*l (128 feats)
__global__ void agg1_kernel(const float* __restrict__ b1) {
    int t = blockIdx.x * blockDim.x + threadIdx.x;
    int w = t >> 5, lane = t & 31;
    if (w >= N_NODES) return;
    int beg = g_row_ptr[w], end = g_row_ptr[w + 1];

    float4 acc = make_float4(0.f, 0.f, 0.f, 0.f);
    for (int j = beg; j < end; j += 32) {
        int n = end - j; if (n > 32) n = 32;
        int eid = (j + lane < end) ? g_eid_src[j + lane] : 0;
        for (int i = 0; i < n; i++) {
            int s = __shfl_sync(0xffffffffu, eid, i);
            float4 v = __ldg(reinterpret_cast<const float4*>(&g_h1[(size_t)s * NH]) + lane);
            acc.x += v.x; acc.y += v.y; acc.z += v.z; acc.w += v.w;
        }
    }
    float nd = g_nd[w];
    float4 bb = __ldg(reinterpret_cast<const float4*>(b1) + lane);
    float4 r;
    r.x = fmaxf(acc.x * nd + bb.x, 0.f);
    r.y = fmaxf(acc.y * nd + bb.y, 0.f);
    r.z = fmaxf(acc.z * nd + bb.z, 0.f);
    r.w = fmaxf(acc.w * nd + bb.w, 0.f);
    *(reinterpret_cast<float4*>(&g_x2[(size_t)w * NH]) + lane) = r;
}

// ---------------- GEMM2: h2 = (x2 @ W2) * ns  (K=128, N=40) ----------------
__global__ __launch_bounds__(256) void gemm2_kernel(const float* __restrict__ W2) {
    __shared__ float W2s[NH * NC];     // 20KB
    __shared__ float xs[8][NH];

    int tid = threadIdx.x;
    for (int i = tid; i < NH * NC; i += 256) W2s[i] = W2[i];
    __syncthreads();

    const int n_tiles = (N_NODES + 7) / 8;
    for (int tile = blockIdx.x; tile < n_tiles; tile += gridDim.x) {
        int row0 = tile * 8;
        #pragma unroll
        for (int i = 0; i < 4; i++) {
            int j = tid + i * 256;
            int r = j >> 7, k = j & 127;
            int row = row0 + r;
            xs[r][k] = (row < N_NODES) ? g_x2[(size_t)row * NH + k] : 0.f;
        }
        __syncthreads();

        for (int j = tid; j < 8 * NC; j += 256) {
            int r = j / NC, c = j % NC;
            int row = row0 + r;
            if (row < N_NODES) {
                float accv = 0.f;
                #pragma unroll 8
                for (int k = 0; k < NH; k++)
                    accv = fmaf(xs[r][k], W2s[k * NC + c], accv);
                g_h2[(size_t)row * NC + c] = accv * g_ns[row];
            }
        }
        __syncthreads();
    }
}

// ---------------- agg2: out[n] = nd[n]*sum_{e->n} h2[src_e] + b2 ------------
// warp per node; lane handles feat `lane`, lanes 0..7 also feat 32+lane
__global__ void agg2_kernel(const float* __restrict__ b2, float* __restrict__ out) {
    int t = blockIdx.x * blockDim.x + threadIdx.x;
    int w = t >> 5, lane = t & 31;
    if (w >= N_NODES) return;
    int beg = g_row_ptr[w], end = g_row_ptr[w + 1];

    float acc0 = 0.f, acc1 = 0.f;
    for (int j = beg; j < end; j += 32) {
        int n = end - j; if (n > 32) n = 32;
        int eid = (j + lane < end) ? g_eid_src[j + lane] : 0;
        for (int i = 0; i < n; i++) {
            int s = __shfl_sync(0xffffffffu, eid, i);
            const float* row = &g_h2[(size_t)s * NC];
            acc0 += __ldg(row + lane);
            if (lane < 8) acc1 += __ldg(row + 32 + lane);
        }
    }
    float nd = g_nd[w];
    out[(size_t)w * NC + lane] = acc0 * nd + __ldg(b2 + lane);
    if (lane < 8)
        out[(size_t)w * NC + 32 + lane] = acc1 * nd + __ldg(b2 + 32 + lane);
}

// ---------------- launch ----------------
extern "C" void kernel_launch(void* const* d_in, const int* in_sizes, int n_in,
                              void* d_out, int out_size) {
    const float* X   = (const float*)d_in[0];
    const float* W1  = (const float*)d_in[1];
    const float* b1  = (const float*)d_in[2];
    const float* W2  = (const float*)d_in[3];
    const float* b2  = (const float*)d_in[4];
    const int*   src = (const int*)  d_in[5];
    const int*   dst = (const int*)  d_in[6];
    float* out = (float*)d_out;

    zero_kernel<<<256, 256>>>();
    deg_kernel<<<(N_EDGES + 255) / 256, 256>>>(src, dst);
    norm_kernel<<<(N_NODES + 255) / 256, 256>>>();
    scan_kernel<<<1, 1024>>>();
    fill_kernel<<<(N_EDGES + 255) / 256, 256>>>(src, dst);
    gemm1_kernel<<<(N_NODES + 127) / 128, 256>>>(X, W1);
    agg1_kernel<<<(N_NODES * 32 + 255) / 256, 256>>>(b1);
    gemm2_kernel<<<2048, 256>>>(W2);
    agg2_kernel<<<(N_NODES * 32 + 255) / 256, 256>>>(b2, out);
}

// round 3
// speedup vs baseline: 1.4572x; 1.2419x over previous
#include <cuda_runtime.h>
#include <math.h>
#include <stdint.h>

#define N_NODES 50000
#define N_EDGES 1600000
#define IN_F    512
#define NH      128
#define NC      40
#define SCAN_B  ((N_NODES + 255) / 256)   // 196 blocks

// ---------------- static scratch (no runtime allocation) ----------------
__device__ int   g_deg_out_i[N_NODES];
__device__ int   g_deg_in_i [N_NODES];
__device__ int   g_cursor   [N_NODES];
__device__ int   g_row_ptr  [N_NODES + 1];
__device__ int   g_bsum     [256];                  // per-block degree sums
__device__ int   g_boff     [256];                  // exclusive block offsets
__device__ int   g_eid_src  [N_EDGES];              // src ids grouped by dst
__device__ float g_ns       [N_NODES];
__device__ float g_nd       [N_NODES];
__device__ float g_h1       [(size_t)N_NODES * NH];
__device__ float g_x2       [(size_t)N_NODES * NH];
__device__ float g_h2       [(size_t)N_NODES * NC];

// ---------------- f32x2 packed math helpers ----------------
__device__ __forceinline__ unsigned long long pack2(float x) {
    unsigned long long r;
    asm("mov.b64 %0, {%1, %1};" : "=l"(r) : "f"(x));
    return r;
}
__device__ __forceinline__ void fma2(unsigned long long& d,
                                     unsigned long long a, unsigned long long b) {
    asm("fma.rn.f32x2 %0, %1, %2, %0;" : "+l"(d) : "l"(a), "l"(b));
}
__device__ __forceinline__ float2 unpack2(unsigned long long v) {
    float lo, hi;
    asm("mov.b64 {%0, %1}, %2;" : "=f"(lo), "=f"(hi) : "l"(v));
    return make_float2(lo, hi);
}

// ---------------- zero counters each call ----------------
__global__ void zero_kernel() {
    int i = blockIdx.x * blockDim.x + threadIdx.x;
    int stride = gridDim.x * blockDim.x;
    for (int j = i; j < N_NODES; j += stride) {
        g_deg_out_i[j] = 0;
        g_deg_in_i [j] = 0;
        g_cursor   [j] = 0;
    }
}

// ---------------- degree histogram ----------------
__global__ void deg_kernel(const int* __restrict__ src, const int* __restrict__ dst) {
    int e = blockIdx.x * blockDim.x + threadIdx.x;
    if (e < N_EDGES) {
        atomicAdd(&g_deg_out_i[src[e]], 1);
        atomicAdd(&g_deg_in_i [dst[e]], 1);
    }
}

__global__ void norm_kernel() {
    int i = blockIdx.x * blockDim.x + threadIdx.x;
    if (i < N_NODES) {
        g_ns[i] = rsqrtf(fmaxf((float)g_deg_out_i[i], 1.f));
        g_nd[i] = rsqrtf(fmaxf((float)g_deg_in_i [i], 1.f));
    }
}

// ---------------- hierarchical scan: deg_in -> row_ptr ----------------
__global__ __launch_bounds__(256) void scan1_kernel() {          // block sums
    __shared__ int s[256];
    int i = blockIdx.x * 256 + threadIdx.x;
    s[threadIdx.x] = (i < N_NODES) ? g_deg_in_i[i] : 0;
    __syncthreads();
    for (int off = 128; off > 0; off >>= 1) {
        if (threadIdx.x < off) s[threadIdx.x] += s[threadIdx.x + off];
        __syncthreads();
    }
    if (threadIdx.x == 0) g_bsum[blockIdx.x] = s[0];
}

__global__ __launch_bounds__(256) void scan2_kernel() {          // scan 196 partials
    __shared__ int s[256];
    int t = threadIdx.x;
    int v = (t < SCAN_B) ? g_bsum[t] : 0;
    s[t] = v;
    __syncthreads();
    for (int off = 1; off < 256; off <<= 1) {
        int u = (t >= off) ? s[t - off] : 0;
        __syncthreads();
        s[t] += u;
        __syncthreads();
    }
    g_boff[t] = s[t] - v;                    // exclusive
    if (t == 255) g_row_ptr[N_NODES] = s[255];
}

__global__ __launch_bounds__(256) void scan3_kernel() {          // local scan + offset
    __shared__ int s[256];
    int t = threadIdx.x;
    int i = blockIdx.x * 256 + t;
    int v = (i < N_NODES) ? g_deg_in_i[i] : 0;
    s[t] = v;
    __syncthreads();
    for (int off = 1; off < 256; off <<= 1) {
        int u = (t >= off) ? s[t - off] : 0;
        __syncthreads();
        s[t] += u;
        __syncthreads();
    }
    if (i < N_NODES) g_row_ptr[i] = g_boff[blockIdx.x] + s[t] - v;
}

// ---------------- bucket edges by dst ----------------
__global__ void fill_kernel(const int* __restrict__ src, const int* __restrict__ dst) {
    int e = blockIdx.x * blockDim.x + threadIdx.x;
    if (e < N_EDGES) {
        int d = dst[e];
        int pos = g_row_ptr[d] + atomicAdd(&g_cursor[d], 1);
        g_eid_src[pos] = src[e];
    }
}

// ---------------- GEMM1: h1 = (X @ W1) * ns[row]  (FFMA2 inner loop) -------
__global__ __launch_bounds__(256) void gemm1_kernel(const float* __restrict__ X,
                                                    const float* __restrict__ W1) {
    __shared__ float As[16][132];
    __shared__ float Bs[16][132];

    const int bm  = blockIdx.x * 128;
    const int tid = threadIdx.x;
    const int tx  = tid % 16;
    const int ty  = tid / 16;

    const int arow  = tid / 4;
    const int acol4 = tid % 4;
    const int brow  = tid / 32;
    const int bcol  = (tid % 32) * 4;

    unsigned long long acc[8][4];     // 8 rows x 4 col-pairs, packed f32x2
    #pragma unroll
    for (int i = 0; i < 8; i++)
        #pragma unroll
        for (int j = 0; j < 4; j++) acc[i][j] = 0ull;

    for (int k0 = 0; k0 < IN_F; k0 += 16) {
        #pragma unroll
        for (int r = 0; r < 2; r++) {
            int m   = arow + r * 64;
            int row = bm + m;
            float4 v = make_float4(0.f, 0.f, 0.f, 0.f);
            if (row < N_NODES)
                v = *reinterpret_cast<const float4*>(&X[(size_t)row * IN_F + k0 + acol4 * 4]);
            As[acol4 * 4 + 0][m] = v.x;
            As[acol4 * 4 + 1][m] = v.y;
            As[acol4 * 4 + 2][m] = v.z;
            As[acol4 * 4 + 3][m] = v.w;
        }
        #pragma unroll
        for (int r = 0; r < 2; r++) {
            int kr = brow + r * 8;
            float4 v = *reinterpret_cast<const float4*>(&W1[(size_t)(k0 + kr) * NH + bcol]);
            *reinterpret_cast<float4*>(&Bs[kr][bcol]) = v;
        }
        __syncthreads();

        #pragma unroll
        for (int k = 0; k < 16; k++) {
            float am[8];
            *reinterpret_cast<float4*>(&am[0]) = *reinterpret_cast<float4*>(&As[k][ty * 8]);
            *reinterpret_cast<float4*>(&am[4]) = *reinterpret_cast<float4*>(&As[k][ty * 8 + 4]);
            unsigned long long bn[4];
            {
                const unsigned long long* bp =
                    reinterpret_cast<const unsigned long long*>(&Bs[k][tx * 8]);
                bn[0] = bp[0]; bn[1] = bp[1]; bn[2] = bp[2]; bn[3] = bp[3];
            }
            unsigned long long a2[8];
            #pragma unroll
            for (int i = 0; i < 8; i++) a2[i] = pack2(am[i]);
            #pragma unroll
            for (int i = 0; i < 8; i++)
                #pragma unroll
                for (int j = 0; j < 4; j++)
                    fma2(acc[i][j], a2[i], bn[j]);
        }
        __syncthreads();
    }

    #pragma unroll
    for (int i = 0; i < 8; i++) {
        int row = bm + ty * 8 + i;
        if (row < N_NODES) {
            float s = g_ns[row];
            #pragma unroll
            for (int j = 0; j < 2; j++) {
                float2 p0 = unpack2(acc[i][j * 2 + 0]);
                float2 p1 = unpack2(acc[i][j * 2 + 1]);
                float4 v = make_float4(p0.x * s, p0.y * s, p1.x * s, p1.y * s);
                *reinterpret_cast<float4*>(&g_h1[(size_t)row * NH + tx * 8 + j * 4]) = v;
            }
        }
    }
}

// ---------------- agg1: x2[n] = relu(nd[n]*sum h1[src_e] + b1) --------------
__global__ void agg1_kernel(const float* __restrict__ b1) {
    int t = blockIdx.x * blockDim.x + threadIdx.x;
    int w = t >> 5, lane = t & 31;
    if (w >= N_NODES) return;
    int beg = g_row_ptr[w], end = g_row_ptr[w + 1];

    float4 acc = make_float4(0.f, 0.f, 0.f, 0.f);
    for (int j = beg; j < end; j += 32) {
        int n = end - j; if (n > 32) n = 32;
        int eid = (j + lane < end) ? g_eid_src[j + lane] : 0;
        for (int i = 0; i < n; i++) {
            int s = __shfl_sync(0xffffffffu, eid, i);
            float4 v = __ldg(reinterpret_cast<const float4*>(&g_h1[(size_t)s * NH]) + lane);
            acc.x += v.x; acc.y += v.y; acc.z += v.z; acc.w += v.w;
        }
    }
    float nd = g_nd[w];
    float4 bb = __ldg(reinterpret_cast<const float4*>(b1) + lane);
    float4 r;
    r.x = fmaxf(acc.x * nd + bb.x, 0.f);
    r.y = fmaxf(acc.y * nd + bb.y, 0.f);
    r.z = fmaxf(acc.z * nd + bb.z, 0.f);
    r.w = fmaxf(acc.w * nd + bb.w, 0.f);
    *(reinterpret_cast<float4*>(&g_x2[(size_t)w * NH]) + lane) = r;
}

// ---------------- GEMM2: h2 = (x2 @ W2) * ns  (FFMA2, col pairs) ------------
__global__ __launch_bounds__(256) void gemm2_kernel(const float* __restrict__ W2) {
    __shared__ float W2s[NH * NC];     // 20KB
    __shared__ float xs[8][NH];

    int tid = threadIdx.x;
    for (int i = tid; i < NH * NC; i += 256) W2s[i] = W2[i];
    __syncthreads();

    const int n_tiles = (N_NODES + 7) / 8;
    for (int tile = blockIdx.x; tile < n_tiles; tile += gridDim.x) {
        int row0 = tile * 8;
        #pragma unroll
        for (int i = 0; i < 4; i++) {
            int j = tid + i * 256;
            int r = j >> 7, k = j & 127;
            int row = row0 + r;
            xs[r][k] = (row < N_NODES) ? g_x2[(size_t)row * NH + k] : 0.f;
        }
        __syncthreads();

        if (tid < 8 * (NC / 2)) {              // 160 threads: row x col-pair
            int r  = tid / (NC / 2);
            int cp = tid % (NC / 2);
            int row = row0 + r;
            if (row < N_NODES) {
                unsigned long long acc = 0ull;
                const unsigned long long* wp =
                    reinterpret_cast<const unsigned long long*>(W2s) + cp;
                #pragma unroll 8
                for (int k = 0; k < NH; k++)
                    fma2(acc, pack2(xs[r][k]), wp[k * (NC / 2)]);
                float2 p = unpack2(acc);
                float s = g_ns[row];
                *reinterpret_cast<float2*>(&g_h2[(size_t)row * NC + cp * 2]) =
                    make_float2(p.x * s, p.y * s);
            }
        }
        __syncthreads();
    }
}

// ---------------- agg2: out[n] = nd[n]*sum h2[src_e] + b2 -------------------
__global__ void agg2_kernel(const float* __restrict__ b2, float* __restrict__ out) {
    int t = blockIdx.x * blockDim.x + threadIdx.x;
    int w = t >> 5, lane = t & 31;
    if (w >= N_NODES) return;
    int beg = g_row_ptr[w], end = g_row_ptr[w + 1];

    float acc0 = 0.f, acc1 = 0.f;
    for (int j = beg; j < end; j += 32) {
        int n = end - j; if (n > 32) n = 32;
        int eid = (j + lane < end) ? g_eid_src[j + lane] : 0;
        for (int i = 0; i < n; i++) {
            int s = __shfl_sync(0xffffffffu, eid, i);
            const float* row = &g_h2[(size_t)s * NC];
            acc0 += __ldg(row + lane);
            if (lane < 8) acc1 += __ldg(row + 32 + lane);
        }
    }
    float nd = g_nd[w];
    out[(size_t)w * NC + lane] = acc0 * nd + __ldg(b2 + lane);
    if (lane < 8)
        out[(size_t)w * NC + 32 + lane] = acc1 * nd + __ldg(b2 + 32 + lane);
}

// ---------------- launch ----------------
extern "C" void kernel_launch(void* const* d_in, const int* in_sizes, int n_in,
                              void* d_out, int out_size) {
    const float* X   = (const float*)d_in[0];
    const float* W1  = (const float*)d_in[1];
    const float* b1  = (const float*)d_in[2];
    const float* W2  = (const float*)d_in[3];
    const float* b2  = (const float*)d_in[4];
    const int*   src = (const int*)  d_in[5];
    const int*   dst = (const int*)  d_in[6];
    float* out = (float*)d_out;

    zero_kernel<<<256, 256>>>();
    deg_kernel<<<(N_EDGES + 255) / 256, 256>>>(src, dst);
    norm_kernel<<<(N_NODES + 255) / 256, 256>>>();
    scan1_kernel<<<SCAN_B, 256>>>();
    scan2_kernel<<<1, 256>>>();
    scan3_kernel<<<SCAN_B, 256>>>();
    fill_kernel<<<(N_EDGES + 255) / 256, 256>>>(src, dst);
    gemm1_kernel<<<(N_NODES + 127) / 128, 256>>>(X, W1);
    agg1_kernel<<<(N_NODES * 32 + 255) / 256, 256>>>(b1);
    gemm2_kernel<<<2048, 256>>>(W2);
    agg2_kernel<<<(N_NODES * 32 + 255) / 256, 256>>>(b2, out);
}

// round 4
// speedup vs baseline: 1.5632x; 1.0727x over previous
#include <cuda_runtime.h>
#include <math.h>
#include <stdint.h>

#define N_NODES 50000
#define N_EDGES 1600000
#define IN_F    512
#define NH      128
#define NC      40
#define SCAN_B  ((N_NODES + 255) / 256)   // 196 blocks

// ---------------- static scratch (no runtime allocation) ----------------
__device__ int   g_deg_out_i[N_NODES];
__device__ int   g_deg_in_i [N_NODES];
__device__ int   g_cursor   [N_NODES];
__device__ int   g_row_ptr  [N_NODES + 1];
__device__ int   g_bsum     [256];
__device__ int   g_boff     [256];
__device__ int2  g_edge     [N_EDGES];              // (src, bits(ns[src])) grouped by dst
__device__ float g_ns       [N_NODES];
__device__ float g_nd       [N_NODES];
__device__ float g_h1       [(size_t)N_NODES * NH]; // X@W1 (unscaled)
__device__ float g_x2       [(size_t)N_NODES * NH]; // relu(agg1*nd + b1)
__device__ float g_h2       [(size_t)N_NODES * NC]; // x2@W2 (unscaled)

// ---------------- f32x2 packed math helpers ----------------
__device__ __forceinline__ unsigned long long pack2(float x) {
    unsigned long long r;
    asm("mov.b64 %0, {%1, %1};" : "=l"(r) : "f"(x));
    return r;
}
__device__ __forceinline__ void fma2(unsigned long long& d,
                                     unsigned long long a, unsigned long long b) {
    asm("fma.rn.f32x2 %0, %1, %2, %0;" : "+l"(d) : "l"(a), "l"(b));
}
__device__ __forceinline__ float2 unpack2(unsigned long long v) {
    float lo, hi;
    asm("mov.b64 {%0, %1}, %2;" : "=f"(lo), "=f"(hi) : "l"(v));
    return make_float2(lo, hi);
}

// ---------------- zero counters each call ----------------
__global__ void zero_kernel() {
    int i = blockIdx.x * blockDim.x + threadIdx.x;
    int stride = gridDim.x * blockDim.x;
    for (int j = i; j < N_NODES; j += stride) {
        g_deg_out_i[j] = 0;
        g_deg_in_i [j] = 0;
        g_cursor   [j] = 0;
    }
}

// ---------------- degree histogram ----------------
__global__ void deg_kernel(const int* __restrict__ src, const int* __restrict__ dst) {
    int e = blockIdx.x * blockDim.x + threadIdx.x;
    if (e < N_EDGES) {
        atomicAdd(&g_deg_out_i[src[e]], 1);
        atomicAdd(&g_deg_in_i [dst[e]], 1);
    }
}

__global__ void norm_kernel() {
    int i = blockIdx.x * blockDim.x + threadIdx.x;
    if (i < N_NODES) {
        g_ns[i] = rsqrtf(fmaxf((float)g_deg_out_i[i], 1.f));
        g_nd[i] = rsqrtf(fmaxf((float)g_deg_in_i [i], 1.f));
    }
}

// ---------------- hierarchical scan: deg_in -> row_ptr ----------------
__global__ __launch_bounds__(256) void scan1_kernel() {
    __shared__ int s[256];
    int i = blockIdx.x * 256 + threadIdx.x;
    s[threadIdx.x] = (i < N_NODES) ? g_deg_in_i[i] : 0;
    __syncthreads();
    for (int off = 128; off > 0; off >>= 1) {
        if (threadIdx.x < off) s[threadIdx.x] += s[threadIdx.x + off];
        __syncthreads();
    }
    if (threadIdx.x == 0) g_bsum[blockIdx.x] = s[0];
}

__global__ __launch_bounds__(256) void scan2_kernel() {
    __shared__ int s[256];
    int t = threadIdx.x;
    int v = (t < SCAN_B) ? g_bsum[t] : 0;
    s[t] = v;
    __syncthreads();
    for (int off = 1; off < 256; off <<= 1) {
        int u = (t >= off) ? s[t - off] : 0;
        __syncthreads();
        s[t] += u;
        __syncthreads();
    }
    g_boff[t] = s[t] - v;
    if (t == 255) g_row_ptr[N_NODES] = s[255];
}

__global__ __launch_bounds__(256) void scan3_kernel() {
    __shared__ int s[256];
    int t = threadIdx.x;
    int i = blockIdx.x * 256 + t;
    int v = (i < N_NODES) ? g_deg_in_i[i] : 0;
    s[t] = v;
    __syncthreads();
    for (int off = 1; off < 256; off <<= 1) {
        int u = (t >= off) ? s[t - off] : 0;
        __syncthreads();
        s[t] += u;
        __syncthreads();
    }
    if (i < N_NODES) g_row_ptr[i] = g_boff[blockIdx.x] + s[t] - v;
}

// ---------------- bucket edges by dst; stash ns[src] alongside -------------
__global__ void fill_kernel(const int* __restrict__ src, const int* __restrict__ dst) {
    int e = blockIdx.x * blockDim.x + threadIdx.x;
    if (e < N_EDGES) {
        int d = dst[e];
        int s = src[e];
        int pos = g_row_ptr[d] + atomicAdd(&g_cursor[d], 1);
        g_edge[pos] = make_int2(s, __float_as_int(g_ns[s]));
    }
}

// ---------------- GEMM1: h1 = X @ W1 (unscaled). 16x4 tile, FFMA2 ----------
// 128x128 block tile, BK=16, 256 threads; thread: 16 rows (8 row-pairs) x 4 cols
__global__ __launch_bounds__(256) void gemm1_kernel(const float* __restrict__ X,
                                                    const float* __restrict__ W1) {
    __shared__ float As[16][132];   // [k][m]
    __shared__ float Bs[16][132];   // [k][n]

    const int bm  = blockIdx.x * 128;
    const int tid = threadIdx.x;
    const int tx  = tid % 32;       // col group: 4 cols
    const int ty  = tid / 32;       // row group: 16 rows

    const int arow  = tid / 4;
    const int acol4 = tid % 4;
    const int brow  = tid / 32;
    const int bcol  = (tid % 32) * 4;

    unsigned long long acc[8][4];   // [row-pair][col], lo=even row, hi=odd row
    #pragma unroll
    for (int i = 0; i < 8; i++)
        #pragma unroll
        for (int j = 0; j < 4; j++) acc[i][j] = 0ull;

    for (int k0 = 0; k0 < IN_F; k0 += 16) {
        #pragma unroll
        for (int r = 0; r < 2; r++) {
            int m   = arow + r * 64;
            int row = bm + m;
            float4 v = make_float4(0.f, 0.f, 0.f, 0.f);
            if (row < N_NODES)
                v = *reinterpret_cast<const float4*>(&X[(size_t)row * IN_F + k0 + acol4 * 4]);
            As[acol4 * 4 + 0][m] = v.x;
            As[acol4 * 4 + 1][m] = v.y;
            As[acol4 * 4 + 2][m] = v.z;
            As[acol4 * 4 + 3][m] = v.w;
        }
        #pragma unroll
        for (int r = 0; r < 2; r++) {
            int kr = brow + r * 8;
            float4 v = *reinterpret_cast<const float4*>(&W1[(size_t)(k0 + kr) * NH + bcol]);
            *reinterpret_cast<float4*>(&Bs[kr][bcol]) = v;
        }
        __syncthreads();

        #pragma unroll
        for (int k = 0; k < 16; k++) {
            // A: 16 consecutive rows -> 8 u64 pairs, direct from smem
            unsigned long long a2[8];
            #pragma unroll
            for (int q = 0; q < 4; q++) {
                float4 fv = *reinterpret_cast<float4*>(&As[k][ty * 16 + q * 4]);
                unsigned long long two[2];
                memcpy(two, &fv, 16);
                a2[q * 2 + 0] = two[0];
                a2[q * 2 + 1] = two[1];
            }
            // B: 4 cols, broadcast-packed
            float4 bv = *reinterpret_cast<float4*>(&Bs[k][tx * 4]);
            unsigned long long b2[4];
            b2[0] = pack2(bv.x); b2[1] = pack2(bv.y);
            b2[2] = pack2(bv.z); b2[3] = pack2(bv.w);
            #pragma unroll
            for (int i = 0; i < 8; i++)
                #pragma unroll
                for (int j = 0; j < 4; j++)
                    fma2(acc[i][j], a2[i], b2[j]);
        }
        __syncthreads();
    }

    // epilogue: unpack row-pairs, store float4 per row (no ns scaling)
    #pragma unroll
    for (int i = 0; i < 8; i++) {
        int r0 = bm + ty * 16 + i * 2;
        float2 c0 = unpack2(acc[i][0]);
        float2 c1 = unpack2(acc[i][1]);
        float2 c2 = unpack2(acc[i][2]);
        float2 c3 = unpack2(acc[i][3]);
        if (r0 < N_NODES)
            *reinterpret_cast<float4*>(&g_h1[(size_t)r0 * NH + tx * 4]) =
                make_float4(c0.x, c1.x, c2.x, c3.x);
        if (r0 + 1 < N_NODES)
            *reinterpret_cast<float4*>(&g_h1[(size_t)(r0 + 1) * NH + tx * 4]) =
                make_float4(c0.y, c1.y, c2.y, c3.y);
    }
}

// ---------------- agg1: x2[n] = relu(nd[n]*sum ns[s]*h1[s] + b1) ------------
__global__ void agg1_kernel(const float* __restrict__ b1) {
    int t = blockIdx.x * blockDim.x + threadIdx.x;
    int w = t >> 5, lane = t & 31;
    if (w >= N_NODES) return;
    int beg = g_row_ptr[w], end = g_row_ptr[w + 1];

    float4 acc = make_float4(0.f, 0.f, 0.f, 0.f);
    for (int j = beg; j < end; j += 32) {
        int n = end - j; if (n > 32) n = 32;
        int2 ed = (j + lane < end) ? g_edge[j + lane] : make_int2(0, 0);
        for (int i = 0; i < n; i++) {
            int   s = __shfl_sync(0xffffffffu, ed.x, i);
            float f = __int_as_float(__shfl_sync(0xffffffffu, ed.y, i));
            float4 v = __ldg(reinterpret_cast<const float4*>(&g_h1[(size_t)s * NH]) + lane);
            acc.x = fmaf(f, v.x, acc.x);
            acc.y = fmaf(f, v.y, acc.y);
            acc.z = fmaf(f, v.z, acc.z);
            acc.w = fmaf(f, v.w, acc.w);
        }
    }
    float nd = g_nd[w];
    float4 bb = __ldg(reinterpret_cast<const float4*>(b1) + lane);
    float4 r;
    r.x = fmaxf(acc.x * nd + bb.x, 0.f);
    r.y = fmaxf(acc.y * nd + bb.y, 0.f);
    r.z = fmaxf(acc.z * nd + bb.z, 0.f);
    r.w = fmaxf(acc.w * nd + bb.w, 0.f);
    *(reinterpret_cast<float4*>(&g_x2[(size_t)w * NH]) + lane) = r;
}

// ---------------- GEMM2: h2 = x2 @ W2 (unscaled; FFMA2 col pairs) -----------
__global__ __launch_bounds__(256) void gemm2_kernel(const float* __restrict__ W2) {
    __shared__ float W2s[NH * NC];     // 20KB
    __shared__ float xs[8][NH];

    int tid = threadIdx.x;
    for (int i = tid; i < NH * NC; i += 256) W2s[i] = W2[i];
    __syncthreads();

    const int n_tiles = (N_NODES + 7) / 8;
    for (int tile = blockIdx.x; tile < n_tiles; tile += gridDim.x) {
        int row0 = tile * 8;
        #pragma unroll
        for (int i = 0; i < 4; i++) {
            int j = tid + i * 256;
            int r = j >> 7, k = j & 127;
            int row = row0 + r;
            xs[r][k] = (row < N_NODES) ? g_x2[(size_t)row * NH + k] : 0.f;
        }
        __syncthreads();

        if (tid < 8 * (NC / 2)) {
            int r  = tid / (NC / 2);
            int cp = tid % (NC / 2);
            int row = row0 + r;
            if (row < N_NODES) {
                unsigned long long acc = 0ull;
                const unsigned long long* wp =
                    reinterpret_cast<const unsigned long long*>(W2s) + cp;
                #pragma unroll 8
                for (int k = 0; k < NH; k++)
                    fma2(acc, pack2(xs[r][k]), wp[k * (NC / 2)]);
                float2 p = unpack2(acc);
                *reinterpret_cast<float2*>(&g_h2[(size_t)row * NC + cp * 2]) = p;
            }
        }
        __syncthreads();
    }
}

// ---------------- agg2: out[n] = nd[n]*sum ns[s]*h2[s] + b2 -----------------
__global__ void agg2_kernel(const float* __restrict__ b2, float* __restrict__ out) {
    int t = blockIdx.x * blockDim.x + threadIdx.x;
    int w = t >> 5, lane = t & 31;
    if (w >= N_NODES) return;
    int beg = g_row_ptr[w], end = g_row_ptr[w + 1];

    float acc0 = 0.f, acc1 = 0.f;
    for (int j = beg; j < end; j += 32) {
        int n = end - j; if (n > 32) n = 32;
        int2 ed = (j + lane < end) ? g_edge[j + lane] : make_int2(0, 0);
        for (int i = 0; i < n; i++) {
            int   s = __shfl_sync(0xffffffffu, ed.x, i);
            float f = __int_as_float(__shfl_sync(0xffffffffu, ed.y, i));
            const float* row = &g_h2[(size_t)s * NC];
            acc0 = fmaf(f, __ldg(row + lane), acc0);
            if (lane < 8) acc1 = fmaf(f, __ldg(row + 32 + lane), acc1);
        }
    }
    float nd = g_nd[w];
    out[(size_t)w * NC + lane] = acc0 * nd + __ldg(b2 + lane);
    if (lane < 8)
        out[(size_t)w * NC + 32 + lane] = acc1 * nd + __ldg(b2 + 32 + lane);
}

// ---------------- launch: fork prep chain alongside gemm1 ------------------
extern "C" void kernel_launch(void* const* d_in, const int* in_sizes, int n_in,
                              void* d_out, int out_size) {
    const float* X   = (const float*)d_in[0];
    const float* W1  = (const float*)d_in[1];
    const float* b1  = (const float*)d_in[2];
    const float* W2  = (const float*)d_in[3];
    const float* b2  = (const float*)d_in[4];
    const int*   src = (const int*)  d_in[5];
    const int*   dst = (const int*)  d_in[6];
    float* out = (float*)d_out;

    static cudaStream_t s_side = nullptr;
    static cudaEvent_t  ev_fork = nullptr, ev_join = nullptr;
    if (s_side == nullptr) {
        cudaStreamCreateWithFlags(&s_side, cudaStreamNonBlocking);
        cudaEventCreateWithFlags(&ev_fork, cudaEventDisableTiming);
        cudaEventCreateWithFlags(&ev_join, cudaEventDisableTiming);
    }

    // fork: side stream runs the graph-prep chain
    cudaEventRecord(ev_fork, 0);
    cudaStreamWaitEvent(s_side, ev_fork, 0);

    zero_kernel<<<256, 256, 0, s_side>>>();
    deg_kernel<<<(N_EDGES + 255) / 256, 256, 0, s_side>>>(src, dst);
    norm_kernel<<<(N_NODES + 255) / 256, 256, 0, s_side>>>();
    scan1_kernel<<<SCAN_B, 256, 0, s_side>>>();
    scan2_kernel<<<1, 256, 0, s_side>>>();
    scan3_kernel<<<SCAN_B, 256, 0, s_side>>>();
    fill_kernel<<<(N_EDGES + 255) / 256, 256, 0, s_side>>>(src, dst);

    // main stream: dense GEMM1 (independent of graph prep)
    gemm1_kernel<<<(N_NODES + 127) / 128, 256>>>(X, W1);

    // join
    cudaEventRecord(ev_join, s_side);
    cudaStreamWaitEvent(0, ev_join, 0);

    agg1_kernel<<<(N_NODES * 32 + 255) / 256, 256>>>(b1);
    gemm2_kernel<<<2048, 256>>>(W2);
    agg2_kernel<<<(N_NODES * 32 + 255) / 256, 256>>>(b2, out);
}

// round 6
// speedup vs baseline: 1.5791x; 1.0102x over previous
#include <cuda_runtime.h>
#include <math.h>
#include <stdint.h>

#define N_NODES 50000
#define N_EDGES 1600000
#define IN_F    512
#define NH      128
#define NC      40
#define SCAN_B  ((N_NODES + 255) / 256)   // 196 blocks

// ---------------- static scratch (no runtime allocation) ----------------
__device__ int   g_deg_out_i[N_NODES];
__device__ int   g_deg_in_i [N_NODES];
__device__ int   g_cursor   [N_NODES];
__device__ int   g_row_ptr  [N_NODES + 1];
__device__ int   g_bsum     [256];
__device__ int   g_boff     [256];
__device__ int2  g_edge     [N_EDGES];              // (src, bits(ns[src])) grouped by dst
__device__ float g_ns       [N_NODES];
__device__ float g_nd       [N_NODES];
__device__ float g_h1       [(size_t)N_NODES * NH]; // X@W1 (unscaled)
__device__ float g_x2       [(size_t)N_NODES * NH]; // relu(agg1*nd + b1)
__device__ float g_h2       [(size_t)N_NODES * NC]; // x2@W2 (unscaled)

// ---------------- f32x2 packed math helpers ----------------
__device__ __forceinline__ unsigned long long pack2(float x) {
    unsigned long long r;
    asm("mov.b64 %0, {%1, %1};" : "=l"(r) : "f"(x));
    return r;
}
__device__ __forceinline__ void fma2(unsigned long long& d,
                                     unsigned long long a, unsigned long long b) {
    asm("fma.rn.f32x2 %0, %1, %2, %0;" : "+l"(d) : "l"(a), "l"(b));
}
__device__ __forceinline__ float2 unpack2(unsigned long long v) {
    float lo, hi;
    asm("mov.b64 {%0, %1}, %2;" : "=f"(lo), "=f"(hi) : "l"(v));
    return make_float2(lo, hi);
}

// ---------------- zero counters each call ----------------
__global__ void zero_kernel() {
    int i = blockIdx.x * blockDim.x + threadIdx.x;
    int stride = gridDim.x * blockDim.x;
    for (int j = i; j < N_NODES; j += stride) {
        g_deg_out_i[j] = 0;
        g_deg_in_i [j] = 0;
        g_cursor   [j] = 0;
    }
}

// ---------------- degree histogram ----------------
__global__ void deg_kernel(const int* __restrict__ src, const int* __restrict__ dst) {
    int e = blockIdx.x * blockDim.x + threadIdx.x;
    if (e < N_EDGES) {
        atomicAdd(&g_deg_out_i[src[e]], 1);
        atomicAdd(&g_deg_in_i [dst[e]], 1);
    }
}

__global__ void norm_kernel() {
    int i = blockIdx.x * blockDim.x + threadIdx.x;
    if (i < N_NODES) {
        g_ns[i] = rsqrtf(fmaxf((float)g_deg_out_i[i], 1.f));
        g_nd[i] = rsqrtf(fmaxf((float)g_deg_in_i [i], 1.f));
    }
}

// ---------------- hierarchical scan: deg_in -> row_ptr ----------------
__global__ __launch_bounds__(256) void scan1_kernel() {
    __shared__ int s[256];
    int i = blockIdx.x * 256 + threadIdx.x;
    s[threadIdx.x] = (i < N_NODES) ? g_deg_in_i[i] : 0;
    __syncthreads();
    for (int off = 128; off > 0; off >>= 1) {
        if (threadIdx.x < off) s[threadIdx.x] += s[threadIdx.x + off];
        __syncthreads();
    }
    if (threadIdx.x == 0) g_bsum[blockIdx.x] = s[0];
}

__global__ __launch_bounds__(256) void scan2_kernel() {
    __shared__ int s[256];
    int t = threadIdx.x;
    int v = (t < SCAN_B) ? g_bsum[t] : 0;
    s[t] = v;
    __syncthreads();
    for (int off = 1; off < 256; off <<= 1) {
        int u = (t >= off) ? s[t - off] : 0;
        __syncthreads();
        s[t] += u;
        __syncthreads();
    }
    g_boff[t] = s[t] - v;
    if (t == 255) g_row_ptr[N_NODES] = s[255];
}

__global__ __launch_bounds__(256) void scan3_kernel() {
    __shared__ int s[256];
    int t = threadIdx.x;
    int i = blockIdx.x * 256 + t;
    int v = (i < N_NODES) ? g_deg_in_i[i] : 0;
    s[t] = v;
    __syncthreads();
    for (int off = 1; off < 256; off <<= 1) {
        int u = (t >= off) ? s[t - off] : 0;
        __syncthreads();
        s[t] += u;
        __syncthreads();
    }
    if (i < N_NODES) g_row_ptr[i] = g_boff[blockIdx.x] + s[t] - v;
}

// ---------------- bucket edges by dst; stash ns[src] alongside -------------
__global__ void fill_kernel(const int* __restrict__ src, const int* __restrict__ dst) {
    int e = blockIdx.x * blockDim.x + threadIdx.x;
    if (e < N_EDGES) {
        int d = dst[e];
        int s = src[e];
        int pos = g_row_ptr[d] + atomicAdd(&g_cursor[d], 1);
        g_edge[pos] = make_int2(s, __float_as_int(g_ns[s]));
    }
}

// ---------------- GEMM1: h1 = X @ W1. Double-buffered FFMA2 ----------------
// 128x128 block tile, BK=16, 256 threads; thread: 16 rows (8 row-pairs) x 4 cols.
// 2-stage smem pipeline: load chunk c+1 while computing chunk c; 1 BAR/chunk.
__global__ __launch_bounds__(256) void gemm1_kernel(const float* __restrict__ X,
                                                    const float* __restrict__ W1) {
    __shared__ float As[2][16][132];   // [stage][k][m]
    __shared__ float Bs[2][16][132];   // [stage][k][n]

    const int bm  = blockIdx.x * 128;
    const int tid = threadIdx.x;
    const int tx  = tid % 32;       // col group: 4 cols
    const int ty  = tid / 32;       // row group: 16 rows

    // A loader: 512 float4 slots (128 rows x 4 float4) / 256 thr = 2 each
    const int ar0 = tid >> 1;            // rows tid/2 and tid/2+...: slot mapping below
    // B loader: 512 float4 slots (16 k x 32 col4) / 256 thr = 2 each

    unsigned long long acc[8][4];
    #pragma unroll
    for (int i = 0; i < 8; i++)
        #pragma unroll
        for (int j = 0; j < 4; j++) acc[i][j] = 0ull;

    // stage loader
    auto load_stage = [&](int st, int k0) {
        #pragma unroll
        for (int i = 0; i < 2; i++) {
            int slot = tid + i * 256;        // 0..511
            int row  = slot >> 2;            // 0..127
            int c4   = slot & 3;             // 0..3
            int gr   = bm + row;
            float4 v = make_float4(0.f, 0.f, 0.f, 0.f);
            if (gr < N_NODES)
                v = *reinterpret_cast<const float4*>(&X[(size_t)gr * IN_F + k0 + c4 * 4]);
            As[st][c4 * 4 + 0][row] = v.x;
            As[st][c4 * 4 + 1][row] = v.y;
            As[st][c4 * 4 + 2][row] = v.z;
            As[st][c4 * 4 + 3][row] = v.w;
        }
        #pragma unroll
        for (int i = 0; i < 2; i++) {
            int slot = tid + i * 256;        // 0..511
            int kr   = slot >> 5;            // 0..15
            int cc   = slot & 31;            // col4
            float4 v = *reinterpret_cast<const float4*>(&W1[(size_t)(k0 + kr) * NH + cc * 4]);
            *reinterpret_cast<float4*>(&Bs[st][kr][cc * 4]) = v;
        }
    };

    load_stage(0, 0);
    __syncthreads();

    const int NCHUNK = IN_F / 16;     // 32
    for (int c = 0; c < NCHUNK; c++) {
        const int cur = c & 1;
        if (c + 1 < NCHUNK)
            load_stage(cur ^ 1, (c + 1) * 16);

        #pragma unroll
        for (int k = 0; k < 16; k++) {
            unsigned long long a2[8];
            #pragma unroll
            for (int q = 0; q < 4; q++) {
                float4 fv = *reinterpret_cast<float4*>(&As[cur][k][ty * 16 + q * 4]);
                unsigned long long two[2];
                memcpy(two, &fv, 16);
                a2[q * 2 + 0] = two[0];
                a2[q * 2 + 1] = two[1];
            }
            float4 bv = *reinterpret_cast<float4*>(&Bs[cur][k][tx * 4]);
            unsigned long long b2[4];
            b2[0] = pack2(bv.x); b2[1] = pack2(bv.y);
            b2[2] = pack2(bv.z); b2[3] = pack2(bv.w);
            #pragma unroll
            for (int i = 0; i < 8; i++)
                #pragma unroll
                for (int j = 0; j < 4; j++)
                    fma2(acc[i][j], a2[i], b2[j]);
        }
        __syncthreads();
    }

    (void)ar0;
    // epilogue: unpack row-pairs, store float4 per row (no ns scaling)
    #pragma unroll
    for (int i = 0; i < 8; i++) {
        int r0 = bm + ty * 16 + i * 2;
        float2 c0 = unpack2(acc[i][0]);
        float2 c1 = unpack2(acc[i][1]);
        float2 c2 = unpack2(acc[i][2]);
        float2 c3 = unpack2(acc[i][3]);
        if (r0 < N_NODES)
            *reinterpret_cast<float4*>(&g_h1[(size_t)r0 * NH + tx * 4]) =
                make_float4(c0.x, c1.x, c2.x, c3.x);
        if (r0 + 1 < N_NODES)
            *reinterpret_cast<float4*>(&g_h1[(size_t)(r0 + 1) * NH + tx * 4]) =
                make_float4(c0.y, c1.y, c2.y, c3.y);
    }
}

// ---------------- agg1: x2[n] = relu(nd[n]*sum ns[s]*h1[s] + b1) ------------
__global__ void agg1_kernel(const float* __restrict__ b1) {
    int t = blockIdx.x * blockDim.x + threadIdx.x;
    int w = t >> 5, lane = t & 31;
    if (w >= N_NODES) return;
    int beg = g_row_ptr[w], end = g_row_ptr[w + 1];

    float4 acc = make_float4(0.f, 0.f, 0.f, 0.f);
    for (int j = beg; j < end; j += 32) {
        int n = end - j; if (n > 32) n = 32;
        int2 ed = (j + lane < end) ? g_edge[j + lane] : make_int2(0, 0);
        #pragma unroll 4
        for (int i = 0; i < n; i++) {
            int   s = __shfl_sync(0xffffffffu, ed.x, i);
            float f = __int_as_float(__shfl_sync(0xffffffffu, ed.y, i));
            float4 v = __ldg(reinterpret_cast<const float4*>(&g_h1[(size_t)s * NH]) + lane);
            acc.x = fmaf(f, v.x, acc.x);
            acc.y = fmaf(f, v.y, acc.y);
            acc.z = fmaf(f, v.z, acc.z);
            acc.w = fmaf(f, v.w, acc.w);
        }
    }
    float nd = g_nd[w];
    float4 bb = __ldg(reinterpret_cast<const float4*>(b1) + lane);
    float4 r;
    r.x = fmaxf(acc.x * nd + bb.x, 0.f);
    r.y = fmaxf(acc.y * nd + bb.y, 0.f);
    r.z = fmaxf(acc.z * nd + bb.z, 0.f);
    r.w = fmaxf(acc.w * nd + bb.w, 0.f);
    *(reinterpret_cast<float4*>(&g_x2[(size_t)w * NH]) + lane) = r;
}

// ---------------- GEMM2: h2 = x2 @ W2 (FFMA2 col pairs) ---------------------
__global__ __launch_bounds__(256) void gemm2_kernel(const float* __restrict__ W2) {
    __shared__ float W2s[NH * NC];
    __shared__ float xs[8][NH];

    int tid = threadIdx.x;
    for (int i = tid; i < NH * NC; i += 256) W2s[i] = W2[i];
    __syncthreads();

    const int n_tiles = (N_NODES + 7) / 8;
    for (int tile = blockIdx.x; tile < n_tiles; tile += gridDim.x) {
        int row0 = tile * 8;
        #pragma unroll
        for (int i = 0; i < 4; i++) {
            int j = tid + i * 256;
            int r = j >> 7, k = j & 127;
            int row = row0 + r;
            xs[r][k] = (row < N_NODES) ? g_x2[(size_t)row * NH + k] : 0.f;
        }
        __syncthreads();

        if (tid < 8 * (NC / 2)) {
            int r  = tid / (NC / 2);
            int cp = tid % (NC / 2);
            int row = row0 + r;
            if (row < N_NODES) {
                unsigned long long acc = 0ull;
                const unsigned long long* wp =
                    reinterpret_cast<const unsigned long long*>(W2s) + cp;
                #pragma unroll 8
                for (int k = 0; k < NH; k++)
                    fma2(acc, pack2(xs[r][k]), wp[k * (NC / 2)]);
                float2 p = unpack2(acc);
                *reinterpret_cast<float2*>(&g_h2[(size_t)row * NC + cp * 2]) = p;
            }
        }
        __syncthreads();
    }
}

// ---------------- agg2: out[n] = nd[n]*sum ns[s]*h2[s] + b2 -----------------
__global__ void agg2_kernel(const float* __restrict__ b2, float* __restrict__ out) {
    int t = blockIdx.x * blockDim.x + threadIdx.x;
    int w = t >> 5, lane = t & 31;
    if (w >= N_NODES) return;
    int beg = g_row_ptr[w], end = g_row_ptr[w + 1];

    float acc0 = 0.f, acc1 = 0.f;
    for (int j = beg; j < end; j += 32) {
        int n = end - j; if (n > 32) n = 32;
        int2 ed = (j + lane < end) ? g_edge[j + lane] : make_int2(0, 0);
        #pragma unroll 4
        for (int i = 0; i < n; i++) {
            int   s = __shfl_sync(0xffffffffu, ed.x, i);
            float f = __int_as_float(__shfl_sync(0xffffffffu, ed.y, i));
            const float* row = &g_h2[(size_t)s * NC];
            acc0 = fmaf(f, __ldg(row + lane), acc0);
            if (lane < 8) acc1 = fmaf(f, __ldg(row + 32 + lane), acc1);
        }
    }
    float nd = g_nd[w];
    out[(size_t)w * NC + lane] = acc0 * nd + __ldg(b2 + lane);
    if (lane < 8)
        out[(size_t)w * NC + 32 + lane] = acc1 * nd + __ldg(b2 + 32 + lane);
}

// ---------------- launch: fork prep chain alongside gemm1 ------------------
extern "C" void kernel_launch(void* const* d_in, const int* in_sizes, int n_in,
                              void* d_out, int out_size) {
    const float* X   = (const float*)d_in[0];
    const float* W1  = (const float*)d_in[1];
    const float* b1  = (const float*)d_in[2];
    const float* W2  = (const float*)d_in[3];
    const float* b2  = (const float*)d_in[4];
    const int*   src = (const int*)  d_in[5];
    const int*   dst = (const int*)  d_in[6];
    float* out = (float*)d_out;

    static cudaStream_t s_side = nullptr;
    static cudaEvent_t  ev_fork = nullptr, ev_join = nullptr;
    if (s_side == nullptr) {
        cudaStreamCreateWithFlags(&s_side, cudaStreamNonBlocking);
        cudaEventCreateWithFlags(&ev_fork, cudaEventDisableTiming);
        cudaEventCreateWithFlags(&ev_join, cudaEventDisableTiming);
    }

    // fork: side stream runs the graph-prep chain
    cudaEventRecord(ev_fork, 0);
    cudaStreamWaitEvent(s_side, ev_fork, 0);

    zero_kernel<<<256, 256, 0, s_side>>>();
    deg_kernel<<<(N_EDGES + 255) / 256, 256, 0, s_side>>>(src, dst);
    norm_kernel<<<(N_NODES + 255) / 256, 256, 0, s_side>>>();
    scan1_kernel<<<SCAN_B, 256, 0, s_side>>>();
    scan2_kernel<<<1, 256, 0, s_side>>>();
    scan3_kernel<<<SCAN_B, 256, 0, s_side>>>();
    fill_kernel<<<(N_EDGES + 255) / 256, 256, 0, s_side>>>(src, dst);

    // main stream: dense GEMM1 (independent of graph prep)
    gemm1_kernel<<<(N_NODES + 127) / 128, 256>>>(X, W1);

    // join
    cudaEventRecord(ev_join, s_side);
    cudaStreamWaitEvent(0, ev_join, 0);

    agg1_kernel<<<(N_NODES * 32 + 255) / 256, 256>>>(b1);
    gemm2_kernel<<<2048, 256>>>(W2);
    agg2_kernel<<<(N_NODES * 32 + 255) / 256, 256>>>(b2, out);
}

// round 7
// speedup vs baseline: 1.8719x; 1.1855x over previous
#include <cuda_runtime.h>
#include <math.h>
#include <stdint.h>

#define N_NODES 50000
#define N_EDGES 1600000
#define IN_F    512
#define NH      128
#define NC      40
#define SCAN_B  ((N_NODES + 255) / 256)   // 196 blocks

// ---------------- static scratch (no runtime allocation) ----------------
__device__ int      g_deg_out_i[N_NODES];
__device__ int      g_deg_in_i [N_NODES];
__device__ int      g_cursor   [N_NODES];
__device__ int      g_row_ptr  [N_NODES + 1];
__device__ int      g_bsum     [256];
__device__ int      g_boff     [256];
__device__ int2     g_edge     [N_EDGES];           // (src, bits(ns[src])) grouped by dst
__device__ float    g_ns       [N_NODES];
__device__ float    g_nd       [N_NODES];
__device__ uint16_t g_w1t_hi   [NH * IN_F];         // W1^T bf16 hi, [n][k]
__device__ uint16_t g_w1t_lo   [NH * IN_F];         // W1^T bf16 lo, [n][k]
__device__ float    g_h1       [(size_t)N_NODES * NH]; // X@W1 (unscaled)
__device__ float    g_x2       [(size_t)N_NODES * NH]; // relu(agg1*nd + b1)
__device__ float    g_h2       [(size_t)N_NODES * NC]; // x2@W2 (unscaled)

// ---------------- small helpers ----------------
__device__ __forceinline__ uint32_t smem_to_u32(const void* p) {
    uint32_t a;
    asm("{ .reg .u64 t; cvta.to.shared.u64 t, %1; cvt.u32.u64 %0, t; }" : "=r"(a) : "l"(p));
    return a;
}
__device__ __forceinline__ uint32_t packbf(float lo_elem, float hi_elem) {
    // returns {bits[15:0]=bf16(lo_elem), bits[31:16]=bf16(hi_elem)}
    uint32_t r;
    asm("cvt.rn.bf16x2.f32 %0, %1, %2;" : "=r"(r) : "f"(hi_elem), "f"(lo_elem));
    return r;
}
__device__ __forceinline__ uint16_t bf16r(float x) {
    uint16_t r;
    asm("cvt.rn.bf16.f32 %0, %1;" : "=h"(r) : "f"(x));
    return r;
}
__device__ __forceinline__ void ldmx4(uint32_t* r, uint32_t addr) {
    asm volatile("ldmatrix.sync.aligned.m8n8.x4.shared.b16 {%0,%1,%2,%3}, [%4];"
                 : "=r"(r[0]), "=r"(r[1]), "=r"(r[2]), "=r"(r[3]) : "r"(addr));
}
__device__ __forceinline__ void mma_bf16(float* d, const uint32_t* a, const uint32_t* b) {
    asm volatile(
        "mma.sync.aligned.m16n8k16.row.col.f32.bf16.bf16.f32 "
        "{%0,%1,%2,%3}, {%4,%5,%6,%7}, {%8,%9}, {%0,%1,%2,%3};"
        : "+f"(d[0]), "+f"(d[1]), "+f"(d[2]), "+f"(d[3])
        : "r"(a[0]), "r"(a[1]), "r"(a[2]), "r"(a[3]), "r"(b[0]), "r"(b[1]));
}
// f32x2 packed helpers (gemm2)
__device__ __forceinline__ unsigned long long pack2(float x) {
    unsigned long long r;
    asm("mov.b64 %0, {%1, %1};" : "=l"(r) : "f"(x));
    return r;
}
__device__ __forceinline__ void fma2(unsigned long long& d,
                                     unsigned long long a, unsigned long long b) {
    asm("fma.rn.f32x2 %0, %1, %2, %0;" : "+l"(d) : "l"(a), "l"(b));
}
__device__ __forceinline__ float2 unpack2(unsigned long long v) {
    float lo, hi;
    asm("mov.b64 {%0, %1}, %2;" : "=f"(lo), "=f"(hi) : "l"(v));
    return make_float2(lo, hi);
}

// ---------------- zero counters each call ----------------
__global__ void zero_kernel() {
    int i = blockIdx.x * blockDim.x + threadIdx.x;
    int stride = gridDim.x * blockDim.x;
    for (int j = i; j < N_NODES; j += stride) {
        g_deg_out_i[j] = 0;
        g_deg_in_i [j] = 0;
        g_cursor   [j] = 0;
    }
}

__global__ void deg_kernel(const int* __restrict__ src, const int* __restrict__ dst) {
    int e = blockIdx.x * blockDim.x + threadIdx.x;
    if (e < N_EDGES) {
        atomicAdd(&g_deg_out_i[src[e]], 1);
        atomicAdd(&g_deg_in_i [dst[e]], 1);
    }
}

__global__ void norm_kernel() {
    int i = blockIdx.x * blockDim.x + threadIdx.x;
    if (i < N_NODES) {
        g_ns[i] = rsqrtf(fmaxf((float)g_deg_out_i[i], 1.f));
        g_nd[i] = rsqrtf(fmaxf((float)g_deg_in_i [i], 1.f));
    }
}

// ---------------- hierarchical scan: deg_in -> row_ptr ----------------
__global__ __launch_bounds__(256) void scan1_kernel() {
    __shared__ int s[256];
    int i = blockIdx.x * 256 + threadIdx.x;
    s[threadIdx.x] = (i < N_NODES) ? g_deg_in_i[i] : 0;
    __syncthreads();
    for (int off = 128; off > 0; off >>= 1) {
        if (threadIdx.x < off) s[threadIdx.x] += s[threadIdx.x + off];
        __syncthreads();
    }
    if (threadIdx.x == 0) g_bsum[blockIdx.x] = s[0];
}

__global__ __launch_bounds__(256) void scan2_kernel() {
    __shared__ int s[256];
    int t = threadIdx.x;
    int v = (t < SCAN_B) ? g_bsum[t] : 0;
    s[t] = v;
    __syncthreads();
    for (int off = 1; off < 256; off <<= 1) {
        int u = (t >= off) ? s[t - off] : 0;
        __syncthreads();
        s[t] += u;
        __syncthreads();
    }
    g_boff[t] = s[t] - v;
    if (t == 255) g_row_ptr[N_NODES] = s[255];
}

__global__ __launch_bounds__(256) void scan3_kernel() {
    __shared__ int s[256];
    int t = threadIdx.x;
    int i = blockIdx.x * 256 + t;
    int v = (i < N_NODES) ? g_deg_in_i[i] : 0;
    s[t] = v;
    __syncthreads();
    for (int off = 1; off < 256; off <<= 1) {
        int u = (t >= off) ? s[t - off] : 0;
        __syncthreads();
        s[t] += u;
        __syncthreads();
    }
    if (i < N_NODES) g_row_ptr[i] = g_boff[blockIdx.x] + s[t] - v;
}

__global__ void fill_kernel(const int* __restrict__ src, const int* __restrict__ dst) {
    int e = blockIdx.x * blockDim.x + threadIdx.x;
    if (e < N_EDGES) {
        int d = dst[e];
        int s = src[e];
        int pos = g_row_ptr[d] + atomicAdd(&g_cursor[d], 1);
        g_edge[pos] = make_int2(s, __float_as_int(g_ns[s]));
    }
}

// ---------------- W1 -> transposed bf16 hi/lo split ----------------
__global__ void w1split_kernel(const float* __restrict__ W1) {
    int i = blockIdx.x * 256 + threadIdx.x;     // over 512*128
    if (i < IN_F * NH) {
        int k = i >> 7, n = i & 127;
        float w = W1[i];
        uint16_t hb = bf16r(w);
        float hf = __uint_as_float((uint32_t)hb << 16);
        uint16_t lb = bf16r(w - hf);
        g_w1t_hi[n * IN_F + k] = hb;
        g_w1t_lo[n * IN_F + k] = lb;
    }
}

// ---------------- GEMM1: h1 = X @ W1 via mma.sync bf16 3-term split --------
// CTA tile 128x128, 8 warps (4 M x 2 N), warp tile 32x64, K-chunk 32, 2 stages.
// smem stage (32KB): Ahi[128][32]bf16 @0, Alo @8192, Bhi[128n][32k] @16384, Blo @24576.
// 64B rows, 16B chunks XOR-swizzled by (row>>1)&3 for conflict-free ldmatrix.
#define G1M_STAGE 32768
#define G1M_SMEM  (2 * G1M_STAGE)

__global__ __launch_bounds__(256) void gemm1_mma_kernel(const float* __restrict__ X) {
    extern __shared__ char smem[];
    const uint32_t sb = smem_to_u32(smem);
    const int tid  = threadIdx.x;
    const int lane = tid & 31;
    const int wid  = tid >> 5;
    const int bm   = blockIdx.x * 128;
    const int mw   = (wid & 3) * 32;     // warp M offset
    const int nw   = (wid >> 2) * 64;    // warp N offset

    float acc[2][8][4];
    #pragma unroll
    for (int i = 0; i < 2; i++)
        #pragma unroll
        for (int j = 0; j < 8; j++)
            #pragma unroll
            for (int q = 0; q < 4; q++) acc[i][j][q] = 0.f;

    // loader: thread t -> row (t>>1), half (t&1) covering 16 floats / 32 bf16-bytes
    const int lrow  = tid >> 1;
    const int lhalf = tid & 1;
    const int lsw   = (lrow >> 1) & 3;

    auto load_stage = [&](int st, int k0) {
        char* stg = smem + st * G1M_STAGE;
        // A: X[bm+row][k0 + half*16 .. +16) fp32 -> bf16 hi/lo
        {
            const int gr = bm + lrow;
            const bool ok = gr < N_NODES;
            const float* xp = &X[(size_t)gr * IN_F + k0 + lhalf * 16];
            #pragma unroll
            for (int q = 0; q < 4; q++) {
                float4 v = ok ? *reinterpret_cast<const float4*>(xp + q * 4)
                              : make_float4(0.f, 0.f, 0.f, 0.f);
                uint32_t h0 = packbf(v.x, v.y);
                uint32_t h1 = packbf(v.z, v.w);
                float l0 = v.x - __uint_as_float(h0 << 16);
                float l1 = v.y - __uint_as_float(h0 & 0xffff0000u);
                float l2 = v.z - __uint_as_float(h1 << 16);
                float l3 = v.w - __uint_as_float(h1 & 0xffff0000u);
                uint32_t p0 = packbf(l0, l1);
                uint32_t p1 = packbf(l2, l3);
                int c16 = lhalf * 2 + (q >> 1);
                uint32_t off = (uint32_t)(lrow * 64 + ((c16 ^ lsw) * 16) + (q & 1) * 8);
                *reinterpret_cast<uint2*>(stg + off)        = make_uint2(h0, h1);
                *reinterpret_cast<uint2*>(stg + 8192 + off) = make_uint2(p0, p1);
            }
        }
        // B: pre-split W1^T bf16 [n][k], copy 32-k slice
        {
            const uint16_t* bh = &g_w1t_hi[lrow * IN_F + k0 + lhalf * 16];
            const uint16_t* bl = &g_w1t_lo[lrow * IN_F + k0 + lhalf * 16];
            #pragma unroll
            for (int q = 0; q < 2; q++) {
                uint4 hv = *reinterpret_cast<const uint4*>(bh + q * 8);
                uint4 lv = *reinterpret_cast<const uint4*>(bl + q * 8);
                int c16 = lhalf * 2 + q;
                uint32_t off = (uint32_t)(lrow * 64 + ((c16 ^ lsw) * 16));
                *reinterpret_cast<uint4*>(stg + 16384 + off) = hv;
                *reinterpret_cast<uint4*>(stg + 24576 + off) = lv;
            }
        }
    };

    load_stage(0, 0);
    __syncthreads();

    // precompute lane pieces for ldmatrix addressing
    const int a_rlane = lane & 15;          // row within 16-row tile
    const int a_kg    = lane >> 4;          // 0/1 -> k+8
    const int b_grp   = lane >> 3;          // 0..3
    const int b_rlane = (b_grp >> 1) * 8 + (lane & 7);
    const int b_kg    = b_grp & 1;

    const int NCHUNK = IN_F / 32;           // 16
    for (int c = 0; c < NCHUNK; c++) {
        const int cur = c & 1;
        if (c + 1 < NCHUNK) load_stage(cur ^ 1, (c + 1) * 32);

        const uint32_t sbase = sb + cur * G1M_STAGE;
        #pragma unroll
        for (int ks = 0; ks < 2; ks++) {
            uint32_t Ahi[2][4], Alo[2][4];
            #pragma unroll
            for (int mt = 0; mt < 2; mt++) {
                int row = mw + mt * 16 + a_rlane;
                uint32_t byteoff = (uint32_t)(row * 64 +
                    (((ks * 2 + a_kg) ^ ((row >> 1) & 3)) * 16));
                ldmx4(Ahi[mt], sbase + byteoff);
                ldmx4(Alo[mt], sbase + 8192 + byteoff);
            }
            uint32_t Bhi[8][2], Blo[8][2];
            #pragma unroll
            for (int ntp = 0; ntp < 4; ntp++) {
                int n = nw + ntp * 16 + b_rlane;
                uint32_t byteoff = (uint32_t)(n * 64 +
                    (((ks * 2 + b_kg) ^ ((n >> 1) & 3)) * 16));
                uint32_t rh[4], rl[4];
                ldmx4(rh, sbase + 16384 + byteoff);
                ldmx4(rl, sbase + 24576 + byteoff);
                Bhi[ntp * 2][0] = rh[0]; Bhi[ntp * 2][1] = rh[1];
                Bhi[ntp * 2 + 1][0] = rh[2]; Bhi[ntp * 2 + 1][1] = rh[3];
                Blo[ntp * 2][0] = rl[0]; Blo[ntp * 2][1] = rl[1];
                Blo[ntp * 2 + 1][0] = rl[2]; Blo[ntp * 2 + 1][1] = rl[3];
            }
            // term 1: hiA * hiB
            #pragma unroll
            for (int mt = 0; mt < 2; mt++)
                #pragma unroll
                for (int nt = 0; nt < 8; nt++)
                    mma_bf16(acc[mt][nt], Ahi[mt], Bhi[nt]);
            // term 2: loA * hiB
            #pragma unroll
            for (int mt = 0; mt < 2; mt++)
                #pragma unroll
                for (int nt = 0; nt < 8; nt++)
                    mma_bf16(acc[mt][nt], Alo[mt], Bhi[nt]);
            // term 3: hiA * loB
            #pragma unroll
            for (int mt = 0; mt < 2; mt++)
                #pragma unroll
                for (int nt = 0; nt < 8; nt++)
                    mma_bf16(acc[mt][nt], Ahi[mt], Blo[nt]);
        }
        __syncthreads();
    }

    // epilogue: D frag -> g_h1
    #pragma unroll
    for (int mt = 0; mt < 2; mt++) {
        int row = bm + mw + mt * 16 + (lane >> 2);
        #pragma unroll
        for (int nt = 0; nt < 8; nt++) {
            int col = nw + nt * 8 + (lane & 3) * 2;
            if (row < N_NODES)
                *reinterpret_cast<float2*>(&g_h1[(size_t)row * NH + col]) =
                    make_float2(acc[mt][nt][0], acc[mt][nt][1]);
            if (row + 8 < N_NODES)
                *reinterpret_cast<float2*>(&g_h1[(size_t)(row + 8) * NH + col]) =
                    make_float2(acc[mt][nt][2], acc[mt][nt][3]);
        }
    }
}

// ---------------- agg1: x2[n] = relu(nd[n]*sum ns[s]*h1[s] + b1) ------------
__global__ void agg1_kernel(const float* __restrict__ b1) {
    int t = blockIdx.x * blockDim.x + threadIdx.x;
    int w = t >> 5, lane = t & 31;
    if (w >= N_NODES) return;
    int beg = g_row_ptr[w], end = g_row_ptr[w + 1];

    float4 acc = make_float4(0.f, 0.f, 0.f, 0.f);
    for (int j = beg; j < end; j += 32) {
        int n = end - j; if (n > 32) n = 32;
        int2 ed = (j + lane < end) ? g_edge[j + lane] : make_int2(0, 0);
        #pragma unroll 4
        for (int i = 0; i < n; i++) {
            int   s = __shfl_sync(0xffffffffu, ed.x, i);
            float f = __int_as_float(__shfl_sync(0xffffffffu, ed.y, i));
            float4 v = __ldg(reinterpret_cast<const float4*>(&g_h1[(size_t)s * NH]) + lane);
            acc.x = fmaf(f, v.x, acc.x);
            acc.y = fmaf(f, v.y, acc.y);
            acc.z = fmaf(f, v.z, acc.z);
            acc.w = fmaf(f, v.w, acc.w);
        }
    }
    float nd = g_nd[w];
    float4 bb = __ldg(reinterpret_cast<const float4*>(b1) + lane);
    float4 r;
    r.x = fmaxf(acc.x * nd + bb.x, 0.f);
    r.y = fmaxf(acc.y * nd + bb.y, 0.f);
    r.z = fmaxf(acc.z * nd + bb.z, 0.f);
    r.w = fmaxf(acc.w * nd + bb.w, 0.f);
    *(reinterpret_cast<float4*>(&g_x2[(size_t)w * NH]) + lane) = r;
}

// ---------------- GEMM2: h2 = x2 @ W2 (FFMA2 col pairs) ---------------------
__global__ __launch_bounds__(256) void gemm2_kernel(const float* __restrict__ W2) {
    __shared__ float W2s[NH * NC];
    __shared__ float xs[8][NH];

    int tid = threadIdx.x;
    for (int i = tid; i < NH * NC; i += 256) W2s[i] = W2[i];
    __syncthreads();

    const int n_tiles = (N_NODES + 7) / 8;
    for (int tile = blockIdx.x; tile < n_tiles; tile += gridDim.x) {
        int row0 = tile * 8;
        #pragma unroll
        for (int i = 0; i < 4; i++) {
            int j = tid + i * 256;
            int r = j >> 7, k = j & 127;
            int row = row0 + r;
            xs[r][k] = (row < N_NODES) ? g_x2[(size_t)row * NH + k] : 0.f;
        }
        __syncthreads();

        if (tid < 8 * (NC / 2)) {
            int r  = tid / (NC / 2);
            int cp = tid % (NC / 2);
            int row = row0 + r;
            if (row < N_NODES) {
                unsigned long long acc = 0ull;
                const unsigned long long* wp =
                    reinterpret_cast<const unsigned long long*>(W2s) + cp;
                #pragma unroll 8
                for (int k = 0; k < NH; k++)
                    fma2(acc, pack2(xs[r][k]), wp[k * (NC / 2)]);
                float2 p = unpack2(acc);
                *reinterpret_cast<float2*>(&g_h2[(size_t)row * NC + cp * 2]) = p;
            }
        }
        __syncthreads();
    }
}

// ---------------- agg2: out[n] = nd[n]*sum ns[s]*h2[s] + b2 -----------------
__global__ void agg2_kernel(const float* __restrict__ b2, float* __restrict__ out) {
    int t = blockIdx.x * blockDim.x + threadIdx.x;
    int w = t >> 5, lane = t & 31;
    if (w >= N_NODES) return;
    int beg = g_row_ptr[w], end = g_row_ptr[w + 1];

    float acc0 = 0.f, acc1 = 0.f;
    for (int j = beg; j < end; j += 32) {
        int n = end - j; if (n > 32) n = 32;
        int2 ed = (j + lane < end) ? g_edge[j + lane] : make_int2(0, 0);
        #pragma unroll 4
        for (int i = 0; i < n; i++) {
            int   s = __shfl_sync(0xffffffffu, ed.x, i);
            float f = __int_as_float(__shfl_sync(0xffffffffu, ed.y, i));
            const float* row = &g_h2[(size_t)s * NC];
            acc0 = fmaf(f, __ldg(row + lane), acc0);
            if (lane < 8) acc1 = fmaf(f, __ldg(row + 32 + lane), acc1);
        }
    }
    float nd = g_nd[w];
    out[(size_t)w * NC + lane] = acc0 * nd + __ldg(b2 + lane);
    if (lane < 8)
        out[(size_t)w * NC + 32 + lane] = acc1 * nd + __ldg(b2 + 32 + lane);
}

// ---------------- launch: fork prep chain alongside gemm1 ------------------
extern "C" void kernel_launch(void* const* d_in, const int* in_sizes, int n_in,
                              void* d_out, int out_size) {
    const float* X   = (const float*)d_in[0];
    const float* W1  = (const float*)d_in[1];
    const float* b1  = (const float*)d_in[2];
    const float* W2  = (const float*)d_in[3];
    const float* b2  = (const float*)d_in[4];
    const int*   src = (const int*)  d_in[5];
    const int*   dst = (const int*)  d_in[6];
    float* out = (float*)d_out;

    static cudaStream_t s_side = nullptr;
    static cudaEvent_t  ev_fork = nullptr, ev_join = nullptr;
    if (s_side == nullptr) {
        cudaStreamCreateWithFlags(&s_side, cudaStreamNonBlocking);
        cudaEventCreateWithFlags(&ev_fork, cudaEventDisableTiming);
        cudaEventCreateWithFlags(&ev_join, cudaEventDisableTiming);
        cudaFuncSetAttribute(gemm1_mma_kernel,
                             cudaFuncAttributeMaxDynamicSharedMemorySize, G1M_SMEM);
    }

    // fork: side stream runs the graph-prep chain
    cudaEventRecord(ev_fork, 0);
    cudaStreamWaitEvent(s_side, ev_fork, 0);

    zero_kernel<<<256, 256, 0, s_side>>>();
    deg_kernel<<<(N_EDGES + 255) / 256, 256, 0, s_side>>>(src, dst);
    norm_kernel<<<(N_NODES + 255) / 256, 256, 0, s_side>>>();
    scan1_kernel<<<SCAN_B, 256, 0, s_side>>>();
    scan2_kernel<<<1, 256, 0, s_side>>>();
    scan3_kernel<<<SCAN_B, 256, 0, s_side>>>();
    fill_kernel<<<(N_EDGES + 255) / 256, 256, 0, s_side>>>(src, dst);

    // main stream: W1 split + tensor-core GEMM1
    w1split_kernel<<<(IN_F * NH + 255) / 256, 256>>>(W1);
    gemm1_mma_kernel<<<(N_NODES + 127) / 128, 256, G1M_SMEM>>>(X);

    // join
    cudaEventRecord(ev_join, s_side);
    cudaStreamWaitEvent(0, ev_join, 0);

    agg1_kernel<<<(N_NODES * 32 + 255) / 256, 256>>>(b1);
    gemm2_kernel<<<2048, 256>>>(W2);
    agg2_kernel<<<(N_NODES * 32 + 255) / 256, 256>>>(b2, out);
}

// round 8
// speedup vs baseline: 1.9498x; 1.0416x over previous
#include <cuda_runtime.h>
#include <math.h>
#include <stdint.h>

#define N_NODES 50000
#define N_EDGES 1600000
#define IN_F    512
#define NH      128
#define NC      40
#define SCAN_B  ((N_NODES + 255) / 256)   // 196 blocks
#define N_HALF  25000

// ---------------- static scratch (no runtime allocation) ----------------
__device__ int      g_deg_out_i[N_NODES];
__device__ int      g_deg_in_i [N_NODES];
__device__ int      g_cursor   [N_NODES];
__device__ int      g_row_ptr  [N_NODES + 1];
__device__ int      g_bsum     [256];
__device__ int      g_boff     [256];
__device__ int2     g_edge     [N_EDGES];           // (src, bits(ns[src])) grouped by dst
__device__ float    g_ns       [N_NODES];
__device__ float    g_nd       [N_NODES];
__device__ uint16_t g_w1t_hi   [NH * IN_F];         // W1^T bf16 hi, [n][k]
__device__ uint16_t g_w1t_lo   [NH * IN_F];         // W1^T bf16 lo, [n][k]
__device__ float    g_h1       [(size_t)N_NODES * NH]; // X@W1 (unscaled)
__device__ float    g_x2       [(size_t)N_NODES * NH]; // relu(agg1*nd + b1)
__device__ float    g_h2       [(size_t)N_NODES * NC]; // x2@W2 (unscaled)

// ---------------- small helpers ----------------
__device__ __forceinline__ uint32_t smem_to_u32(const void* p) {
    uint32_t a;
    asm("{ .reg .u64 t; cvta.to.shared.u64 t, %1; cvt.u32.u64 %0, t; }" : "=r"(a) : "l"(p));
    return a;
}
__device__ __forceinline__ uint32_t packbf(float lo_elem, float hi_elem) {
    uint32_t r;
    asm("cvt.rn.bf16x2.f32 %0, %1, %2;" : "=r"(r) : "f"(hi_elem), "f"(lo_elem));
    return r;
}
__device__ __forceinline__ uint16_t bf16r(float x) {
    uint16_t r;
    asm("cvt.rn.bf16.f32 %0, %1;" : "=h"(r) : "f"(x));
    return r;
}
__device__ __forceinline__ void ldmx4(uint32_t* r, uint32_t addr) {
    asm volatile("ldmatrix.sync.aligned.m8n8.x4.shared.b16 {%0,%1,%2,%3}, [%4];"
                 : "=r"(r[0]), "=r"(r[1]), "=r"(r[2]), "=r"(r[3]) : "r"(addr));
}
__device__ __forceinline__ void mma_bf16(float* d, const uint32_t* a, const uint32_t* b) {
    asm volatile(
        "mma.sync.aligned.m16n8k16.row.col.f32.bf16.bf16.f32 "
        "{%0,%1,%2,%3}, {%4,%5,%6,%7}, {%8,%9}, {%0,%1,%2,%3};"
        : "+f"(d[0]), "+f"(d[1]), "+f"(d[2]), "+f"(d[3])
        : "r"(a[0]), "r"(a[1]), "r"(a[2]), "r"(a[3]), "r"(b[0]), "r"(b[1]));
}
__device__ __forceinline__ unsigned long long pack2(float x) {
    unsigned long long r;
    asm("mov.b64 %0, {%1, %1};" : "=l"(r) : "f"(x));
    return r;
}
__device__ __forceinline__ void fma2(unsigned long long& d,
                                     unsigned long long a, unsigned long long b) {
    asm("fma.rn.f32x2 %0, %1, %2, %0;" : "+l"(d) : "l"(a), "l"(b));
}
__device__ __forceinline__ float2 unpack2(unsigned long long v) {
    float lo, hi;
    asm("mov.b64 {%0, %1}, %2;" : "=f"(lo), "=f"(hi) : "l"(v));
    return make_float2(lo, hi);
}

// ---------------- zero counters each call ----------------
__global__ void zero_kernel() {
    int i = blockIdx.x * blockDim.x + threadIdx.x;
    int stride = gridDim.x * blockDim.x;
    for (int j = i; j < N_NODES; j += stride) {
        g_deg_out_i[j] = 0;
        g_deg_in_i [j] = 0;
        g_cursor   [j] = 0;
    }
}

__global__ void deg_kernel(const int* __restrict__ src, const int* __restrict__ dst) {
    int e = blockIdx.x * blockDim.x + threadIdx.x;
    if (e < N_EDGES) {
        atomicAdd(&g_deg_out_i[src[e]], 1);
        atomicAdd(&g_deg_in_i [dst[e]], 1);
    }
}

__global__ void norm_kernel() {
    int i = blockIdx.x * blockDim.x + threadIdx.x;
    if (i < N_NODES) {
        g_ns[i] = rsqrtf(fmaxf((float)g_deg_out_i[i], 1.f));
        g_nd[i] = rsqrtf(fmaxf((float)g_deg_in_i [i], 1.f));
    }
}

// ---------------- hierarchical scan: deg_in -> row_ptr ----------------
__global__ __launch_bounds__(256) void scan1_kernel() {
    __shared__ int s[256];
    int i = blockIdx.x * 256 + threadIdx.x;
    s[threadIdx.x] = (i < N_NODES) ? g_deg_in_i[i] : 0;
    __syncthreads();
    for (int off = 128; off > 0; off >>= 1) {
        if (threadIdx.x < off) s[threadIdx.x] += s[threadIdx.x + off];
        __syncthreads();
    }
    if (threadIdx.x == 0) g_bsum[blockIdx.x] = s[0];
}

__global__ __launch_bounds__(256) void scan2_kernel() {
    __shared__ int s[256];
    int t = threadIdx.x;
    int v = (t < SCAN_B) ? g_bsum[t] : 0;
    s[t] = v;
    __syncthreads();
    for (int off = 1; off < 256; off <<= 1) {
        int u = (t >= off) ? s[t - off] : 0;
        __syncthreads();
        s[t] += u;
        __syncthreads();
    }
    g_boff[t] = s[t] - v;
    if (t == 255) g_row_ptr[N_NODES] = s[255];
}

__global__ __launch_bounds__(256) void scan3_kernel() {
    __shared__ int s[256];
    int t = threadIdx.x;
    int i = blockIdx.x * 256 + t;
    int v = (i < N_NODES) ? g_deg_in_i[i] : 0;
    s[t] = v;
    __syncthreads();
    for (int off = 1; off < 256; off <<= 1) {
        int u = (t >= off) ? s[t - off] : 0;
        __syncthreads();
        s[t] += u;
        __syncthreads();
    }
    if (i < N_NODES) g_row_ptr[i] = g_boff[blockIdx.x] + s[t] - v;
}

__global__ void fill_kernel(const int* __restrict__ src, const int* __restrict__ dst) {
    int e = blockIdx.x * blockDim.x + threadIdx.x;
    if (e < N_EDGES) {
        int d = dst[e];
        int s = src[e];
        int pos = g_row_ptr[d] + atomicAdd(&g_cursor[d], 1);
        g_edge[pos] = make_int2(s, __float_as_int(g_ns[s]));
    }
}

// ---------------- W1 -> transposed bf16 hi/lo split ----------------
__global__ void w1split_kernel(const float* __restrict__ W1) {
    int i = blockIdx.x * 256 + threadIdx.x;     // over 512*128
    if (i < IN_F * NH) {
        int k = i >> 7, n = i & 127;
        float w = W1[i];
        uint16_t hb = bf16r(w);
        float hf = __uint_as_float((uint32_t)hb << 16);
        uint16_t lb = bf16r(w - hf);
        g_w1t_hi[n * IN_F + k] = hb;
        g_w1t_lo[n * IN_F + k] = lb;
    }
}

// ---------------- GEMM1: h1 = X @ W1 via mma.sync bf16 3-term split --------
#define G1M_STAGE 32768
#define G1M_SMEM  (2 * G1M_STAGE)

__global__ __launch_bounds__(256) void gemm1_mma_kernel(const float* __restrict__ X) {
    extern __shared__ char smem[];
    const uint32_t sb = smem_to_u32(smem);
    const int tid  = threadIdx.x;
    const int lane = tid & 31;
    const int wid  = tid >> 5;
    const int bm   = blockIdx.x * 128;
    const int mw   = (wid & 3) * 32;     // warp M offset
    const int nw   = (wid >> 2) * 64;    // warp N offset

    float acc[2][8][4];
    #pragma unroll
    for (int i = 0; i < 2; i++)
        #pragma unroll
        for (int j = 0; j < 8; j++)
            #pragma unroll
            for (int q = 0; q < 4; q++) acc[i][j][q] = 0.f;

    const int lrow  = tid >> 1;
    const int lhalf = tid & 1;
    const int lsw   = (lrow >> 1) & 3;

    auto load_stage = [&](int st, int k0) {
        char* stg = smem + st * G1M_STAGE;
        {
            const int gr = bm + lrow;
            const bool ok = gr < N_NODES;
            const float* xp = &X[(size_t)gr * IN_F + k0 + lhalf * 16];
            #pragma unroll
            for (int q = 0; q < 4; q++) {
                float4 v = ok ? *reinterpret_cast<const float4*>(xp + q * 4)
                              : make_float4(0.f, 0.f, 0.f, 0.f);
                uint32_t h0 = packbf(v.x, v.y);
                uint32_t h1 = packbf(v.z, v.w);
                float l0 = v.x - __uint_as_float(h0 << 16);
                float l1 = v.y - __uint_as_float(h0 & 0xffff0000u);
                float l2 = v.z - __uint_as_float(h1 << 16);
                float l3 = v.w - __uint_as_float(h1 & 0xffff0000u);
                uint32_t p0 = packbf(l0, l1);
                uint32_t p1 = packbf(l2, l3);
                int c16 = lhalf * 2 + (q >> 1);
                uint32_t off = (uint32_t)(lrow * 64 + ((c16 ^ lsw) * 16) + (q & 1) * 8);
                *reinterpret_cast<uint2*>(stg + off)        = make_uint2(h0, h1);
                *reinterpret_cast<uint2*>(stg + 8192 + off) = make_uint2(p0, p1);
            }
        }
        {
            const uint16_t* bh = &g_w1t_hi[lrow * IN_F + k0 + lhalf * 16];
            const uint16_t* bl = &g_w1t_lo[lrow * IN_F + k0 + lhalf * 16];
            #pragma unroll
            for (int q = 0; q < 2; q++) {
                uint4 hv = *reinterpret_cast<const uint4*>(bh + q * 8);
                uint4 lv = *reinterpret_cast<const uint4*>(bl + q * 8);
                int c16 = lhalf * 2 + q;
                uint32_t off = (uint32_t)(lrow * 64 + ((c16 ^ lsw) * 16));
                *reinterpret_cast<uint4*>(stg + 16384 + off) = hv;
                *reinterpret_cast<uint4*>(stg + 24576 + off) = lv;
            }
        }
    };

    load_stage(0, 0);
    __syncthreads();

    const int a_rlane = lane & 15;
    const int a_kg    = lane >> 4;
    const int b_grp   = lane >> 3;
    const int b_rlane = (b_grp >> 1) * 8 + (lane & 7);
    const int b_kg    = b_grp & 1;

    const int NCHUNK = IN_F / 32;           // 16
    for (int c = 0; c < NCHUNK; c++) {
        const int cur = c & 1;
        if (c + 1 < NCHUNK) load_stage(cur ^ 1, (c + 1) * 32);

        const uint32_t sbase = sb + cur * G1M_STAGE;
        #pragma unroll
        for (int ks = 0; ks < 2; ks++) {
            uint32_t Ahi[2][4], Alo[2][4];
            #pragma unroll
            for (int mt = 0; mt < 2; mt++) {
                int row = mw + mt * 16 + a_rlane;
                uint32_t byteoff = (uint32_t)(row * 64 +
                    (((ks * 2 + a_kg) ^ ((row >> 1) & 3)) * 16));
                ldmx4(Ahi[mt], sbase + byteoff);
                ldmx4(Alo[mt], sbase + 8192 + byteoff);
            }
            uint32_t Bhi[8][2], Blo[8][2];
            #pragma unroll
            for (int ntp = 0; ntp < 4; ntp++) {
                int n = nw + ntp * 16 + b_rlane;
                uint32_t byteoff = (uint32_t)(n * 64 +
                    (((ks * 2 + b_kg) ^ ((n >> 1) & 3)) * 16));
                uint32_t rh[4], rl[4];
                ldmx4(rh, sbase + 16384 + byteoff);
                ldmx4(rl, sbase + 24576 + byteoff);
                Bhi[ntp * 2][0] = rh[0]; Bhi[ntp * 2][1] = rh[1];
                Bhi[ntp * 2 + 1][0] = rh[2]; Bhi[ntp * 2 + 1][1] = rh[3];
                Blo[ntp * 2][0] = rl[0]; Blo[ntp * 2][1] = rl[1];
                Blo[ntp * 2 + 1][0] = rl[2]; Blo[ntp * 2 + 1][1] = rl[3];
            }
            #pragma unroll
            for (int mt = 0; mt < 2; mt++)
                #pragma unroll
                for (int nt = 0; nt < 8; nt++)
                    mma_bf16(acc[mt][nt], Ahi[mt], Bhi[nt]);
            #pragma unroll
            for (int mt = 0; mt < 2; mt++)
                #pragma unroll
                for (int nt = 0; nt < 8; nt++)
                    mma_bf16(acc[mt][nt], Alo[mt], Bhi[nt]);
            #pragma unroll
            for (int mt = 0; mt < 2; mt++)
                #pragma unroll
                for (int nt = 0; nt < 8; nt++)
                    mma_bf16(acc[mt][nt], Ahi[mt], Blo[nt]);
        }
        __syncthreads();
    }

    #pragma unroll
    for (int mt = 0; mt < 2; mt++) {
        int row = bm + mw + mt * 16 + (lane >> 2);
        #pragma unroll
        for (int nt = 0; nt < 8; nt++) {
            int col = nw + nt * 8 + (lane & 3) * 2;
            if (row < N_NODES)
                *reinterpret_cast<float2*>(&g_h1[(size_t)row * NH + col]) =
                    make_float2(acc[mt][nt][0], acc[mt][nt][1]);
            if (row + 8 < N_NODES)
                *reinterpret_cast<float2*>(&g_h1[(size_t)(row + 8) * NH + col]) =
                    make_float2(acc[mt][nt][2], acc[mt][nt][3]);
        }
    }
}

// ---------------- agg1 over [base, base+count): FFMA2 inner loop -----------
__global__ void agg1_kernel(const float* __restrict__ b1, int base, int count) {
    int t = blockIdx.x * blockDim.x + threadIdx.x;
    int w = (t >> 5);
    int lane = t & 31;
    if (w >= count) return;
    w += base;
    int beg = g_row_ptr[w], end = g_row_ptr[w + 1];

    unsigned long long a01 = 0ull, a23 = 0ull;
    for (int j = beg; j < end; j += 32) {
        int n = end - j; if (n > 32) n = 32;
        int2 ed = (j + lane < end) ? g_edge[j + lane] : make_int2(0, 0);
        #pragma unroll 8
        for (int i = 0; i < n; i++) {
            int   s = __shfl_sync(0xffffffffu, ed.x, i);
            float f = __int_as_float(__shfl_sync(0xffffffffu, ed.y, i));
            uint4 v = __ldg(reinterpret_cast<const uint4*>(&g_h1[(size_t)s * NH]) + lane);
            unsigned long long v01 = ((unsigned long long)v.y << 32) | v.x;
            unsigned long long v23 = ((unsigned long long)v.w << 32) | v.z;
            unsigned long long pf = pack2(f);
            fma2(a01, pf, v01);
            fma2(a23, pf, v23);
        }
    }
    float nd = g_nd[w];
    float4 bb = __ldg(reinterpret_cast<const float4*>(b1) + lane);
    float2 p01 = unpack2(a01);
    float2 p23 = unpack2(a23);
    float4 r;
    r.x = fmaxf(p01.x * nd + bb.x, 0.f);
    r.y = fmaxf(p01.y * nd + bb.y, 0.f);
    r.z = fmaxf(p23.x * nd + bb.z, 0.f);
    r.w = fmaxf(p23.y * nd + bb.w, 0.f);
    *(reinterpret_cast<float4*>(&g_x2[(size_t)w * NH]) + lane) = r;
}

// ---------------- GEMM2 over [base, base+count) -----------------------------
__global__ __launch_bounds__(256) void gemm2_kernel(const float* __restrict__ W2,
                                                    int base, int count) {
    __shared__ float W2s[NH * NC];
    __shared__ float xs[8][NH];

    int tid = threadIdx.x;
    for (int i = tid; i < NH * NC; i += 256) W2s[i] = W2[i];
    __syncthreads();

    const int n_tiles = (count + 7) / 8;
    for (int tile = blockIdx.x; tile < n_tiles; tile += gridDim.x) {
        int row0 = base + tile * 8;
        int lim  = base + count;
        #pragma unroll
        for (int i = 0; i < 4; i++) {
            int j = tid + i * 256;
            int r = j >> 7, k = j & 127;
            int row = row0 + r;
            xs[r][k] = (row < lim) ? g_x2[(size_t)row * NH + k] : 0.f;
        }
        __syncthreads();

        if (tid < 8 * (NC / 2)) {
            int r  = tid / (NC / 2);
            int cp = tid % (NC / 2);
            int row = row0 + r;
            if (row < lim) {
                unsigned long long acc = 0ull;
                const unsigned long long* wp =
                    reinterpret_cast<const unsigned long long*>(W2s) + cp;
                #pragma unroll 8
                for (int k = 0; k < NH; k++)
                    fma2(acc, pack2(xs[r][k]), wp[k * (NC / 2)]);
                float2 p = unpack2(acc);
                *reinterpret_cast<float2*>(&g_h2[(size_t)row * NC + cp * 2]) = p;
            }
        }
        __syncthreads();
    }
}

// ---------------- agg2: out[n] = nd[n]*sum ns[s]*h2[s] + b2 -----------------
__global__ void agg2_kernel(const float* __restrict__ b2, float* __restrict__ out) {
    int t = blockIdx.x * blockDim.x + threadIdx.x;
    int w = t >> 5, lane = t & 31;
    if (w >= N_NODES) return;
    int beg = g_row_ptr[w], end = g_row_ptr[w + 1];

    float acc0 = 0.f, acc1 = 0.f;
    for (int j = beg; j < end; j += 32) {
        int n = end - j; if (n > 32) n = 32;
        int2 ed = (j + lane < end) ? g_edge[j + lane] : make_int2(0, 0);
        #pragma unroll 8
        for (int i = 0; i < n; i++) {
            int   s = __shfl_sync(0xffffffffu, ed.x, i);
            float f = __int_as_float(__shfl_sync(0xffffffffu, ed.y, i));
            const float* row = &g_h2[(size_t)s * NC];
            acc0 = fmaf(f, __ldg(row + lane), acc0);
            if (lane < 8) acc1 = fmaf(f, __ldg(row + 32 + lane), acc1);
        }
    }
    float nd = g_nd[w];
    out[(size_t)w * NC + lane] = acc0 * nd + __ldg(b2 + lane);
    if (lane < 8)
        out[(size_t)w * NC + 32 + lane] = acc1 * nd + __ldg(b2 + 32 + lane);
}

// ---------------- launch ----------------
extern "C" void kernel_launch(void* const* d_in, const int* in_sizes, int n_in,
                              void* d_out, int out_size) {
    const float* X   = (const float*)d_in[0];
    const float* W1  = (const float*)d_in[1];
    const float* b1  = (const float*)d_in[2];
    const float* W2  = (const float*)d_in[3];
    const float* b2  = (const float*)d_in[4];
    const int*   src = (const int*)  d_in[5];
    const int*   dst = (const int*)  d_in[6];
    float* out = (float*)d_out;

    static cudaStream_t s_side = nullptr;
    static cudaEvent_t  ev_fork = nullptr, ev_join = nullptr;
    static cudaEvent_t  ev_a = nullptr, ev_g2a = nullptr;
    if (s_side == nullptr) {
        cudaStreamCreateWithFlags(&s_side, cudaStreamNonBlocking);
        cudaEventCreateWithFlags(&ev_fork, cudaEventDisableTiming);
        cudaEventCreateWithFlags(&ev_join, cudaEventDisableTiming);
        cudaEventCreateWithFlags(&ev_a, cudaEventDisableTiming);
        cudaEventCreateWithFlags(&ev_g2a, cudaEventDisableTiming);
        cudaFuncSetAttribute(gemm1_mma_kernel,
                             cudaFuncAttributeMaxDynamicSharedMemorySize, G1M_SMEM);
    }

    // fork: side stream runs the graph-prep chain
    cudaEventRecord(ev_fork, 0);
    cudaStreamWaitEvent(s_side, ev_fork, 0);

    zero_kernel<<<256, 256, 0, s_side>>>();
    deg_kernel<<<(N_EDGES + 255) / 256, 256, 0, s_side>>>(src, dst);
    norm_kernel<<<(N_NODES + 255) / 256, 256, 0, s_side>>>();
    scan1_kernel<<<SCAN_B, 256, 0, s_side>>>();
    scan2_kernel<<<1, 256, 0, s_side>>>();
    scan3_kernel<<<SCAN_B, 256, 0, s_side>>>();
    fill_kernel<<<(N_EDGES + 255) / 256, 256, 0, s_side>>>(src, dst);

    // main stream: W1 split + tensor-core GEMM1
    w1split_kernel<<<(IN_F * NH + 255) / 256, 256>>>(W1);
    gemm1_mma_kernel<<<(N_NODES + 127) / 128, 256, G1M_SMEM>>>(X);

    // join
    cudaEventRecord(ev_join, s_side);
    cudaStreamWaitEvent(0, ev_join, 0);

    // agg1 half A; gemm2(A) overlaps agg1 half B
    agg1_kernel<<<(N_HALF * 32 + 255) / 256, 256>>>(b1, 0, N_HALF);
    cudaEventRecord(ev_a, 0);
    cudaStreamWaitEvent(s_side, ev_a, 0);
    gemm2_kernel<<<1024, 256, 0, s_side>>>(W2, 0, N_HALF);

    agg1_kernel<<<((N_NODES - N_HALF) * 32 + 255) / 256, 256>>>(b1, N_HALF, N_NODES - N_HALF);
    gemm2_kernel<<<1024, 256>>>(W2, N_HALF, N_NODES - N_HALF);

    cudaEventRecord(ev_g2a, s_side);
    cudaStreamWaitEvent(0, ev_g2a, 0);

    agg2_kernel<<<(N_NODES * 32 + 255) / 256, 256>>>(b2, out);
}

// round 9
// speedup vs baseline: 2.0227x; 1.0374x over previous
#include <cuda_runtime.h>
#include <cuda_fp16.h>
#include <math.h>
#include <stdint.h>

#define N_NODES 50000
#define N_EDGES 1600000
#define IN_F    512
#define NH      128
#define NC      40
#define SCAN_B  ((N_NODES + 255) / 256)   // 196 blocks
#define N_HALF  25000

// ---------------- static scratch (no runtime allocation) ----------------
__device__ int      g_deg_out_i[N_NODES];
__device__ int      g_deg_in_i [N_NODES];
__device__ int      g_cursor   [N_NODES];
__device__ int      g_row_ptr  [N_NODES + 1];
__device__ int      g_bsum     [256];
__device__ int      g_boff     [256];
__device__ int2     g_edge     [N_EDGES];           // (src, bits(ns[src])) grouped by dst
__device__ float    g_ns       [N_NODES];
__device__ float    g_nd       [N_NODES];
__device__ uint16_t g_w1t_hi   [NH * IN_F];         // W1^T bf16 hi, [n][k]
__device__ uint16_t g_w1t_lo   [NH * IN_F];         // W1^T bf16 lo, [n][k]
__device__ __half   g_h1       [(size_t)N_NODES * NH]; // X@W1 (unscaled, fp16)
__device__ float    g_x2       [(size_t)N_NODES * NH]; // relu(agg1*nd + b1)
__device__ float    g_h2       [(size_t)N_NODES * NC]; // x2@W2 (unscaled)

// ---------------- small helpers ----------------
__device__ __forceinline__ uint32_t smem_to_u32(const void* p) {
    uint32_t a;
    asm("{ .reg .u64 t; cvta.to.shared.u64 t, %1; cvt.u32.u64 %0, t; }" : "=r"(a) : "l"(p));
    return a;
}
__device__ __forceinline__ uint32_t packbf(float lo_elem, float hi_elem) {
    uint32_t r;
    asm("cvt.rn.bf16x2.f32 %0, %1, %2;" : "=r"(r) : "f"(hi_elem), "f"(lo_elem));
    return r;
}
__device__ __forceinline__ uint16_t bf16r(float x) {
    uint16_t r;
    asm("cvt.rn.bf16.f32 %0, %1;" : "=h"(r) : "f"(x));
    return r;
}
__device__ __forceinline__ void ldmx4(uint32_t* r, uint32_t addr) {
    asm volatile("ldmatrix.sync.aligned.m8n8.x4.shared.b16 {%0,%1,%2,%3}, [%4];"
                 : "=r"(r[0]), "=r"(r[1]), "=r"(r[2]), "=r"(r[3]) : "r"(addr));
}
__device__ __forceinline__ void mma_bf16(float* d, const uint32_t* a, const uint32_t* b) {
    asm volatile(
        "mma.sync.aligned.m16n8k16.row.col.f32.bf16.bf16.f32 "
        "{%0,%1,%2,%3}, {%4,%5,%6,%7}, {%8,%9}, {%0,%1,%2,%3};"
        : "+f"(d[0]), "+f"(d[1]), "+f"(d[2]), "+f"(d[3])
        : "r"(a[0]), "r"(a[1]), "r"(a[2]), "r"(a[3]), "r"(b[0]), "r"(b[1]));
}
__device__ __forceinline__ unsigned long long pack2(float x) {
    unsigned long long r;
    asm("mov.b64 %0, {%1, %1};" : "=l"(r) : "f"(x));
    return r;
}
__device__ __forceinline__ unsigned long long packf2(float lo, float hi) {
    unsigned long long r;
    asm("mov.b64 %0, {%1, %2};" : "=l"(r) : "f"(lo), "f"(hi));
    return r;
}
__device__ __forceinline__ void fma2(unsigned long long& d,
                                     unsigned long long a, unsigned long long b) {
    asm("fma.rn.f32x2 %0, %1, %2, %0;" : "+l"(d) : "l"(a), "l"(b));
}
__device__ __forceinline__ float2 unpack2(unsigned long long v) {
    float lo, hi;
    asm("mov.b64 {%0, %1}, %2;" : "=f"(lo), "=f"(hi) : "l"(v));
    return make_float2(lo, hi);
}

// ---------------- zero counters each call ----------------
__global__ void zero_kernel() {
    int i = blockIdx.x * blockDim.x + threadIdx.x;
    int stride = gridDim.x * blockDim.x;
    for (int j = i; j < N_NODES; j += stride) {
        g_deg_out_i[j] = 0;
        g_deg_in_i [j] = 0;
        g_cursor   [j] = 0;
    }
}

__global__ void deg_kernel(const int* __restrict__ src, const int* __restrict__ dst) {
    int e = blockIdx.x * blockDim.x + threadIdx.x;
    if (e < N_EDGES) {
        atomicAdd(&g_deg_out_i[src[e]], 1);
        atomicAdd(&g_deg_in_i [dst[e]], 1);
    }
}

__global__ void norm_kernel() {
    int i = blockIdx.x * blockDim.x + threadIdx.x;
    if (i < N_NODES) {
        g_ns[i] = rsqrtf(fmaxf((float)g_deg_out_i[i], 1.f));
        g_nd[i] = rsqrtf(fmaxf((float)g_deg_in_i [i], 1.f));
    }
}

// ---------------- hierarchical scan: deg_in -> row_ptr ----------------
__global__ __launch_bounds__(256) void scan1_kernel() {
    __shared__ int s[256];
    int i = blockIdx.x * 256 + threadIdx.x;
    s[threadIdx.x] = (i < N_NODES) ? g_deg_in_i[i] : 0;
    __syncthreads();
    for (int off = 128; off > 0; off >>= 1) {
        if (threadIdx.x < off) s[threadIdx.x] += s[threadIdx.x + off];
        __syncthreads();
    }
    if (threadIdx.x == 0) g_bsum[blockIdx.x] = s[0];
}

__global__ __launch_bounds__(256) void scan2_kernel() {
    __shared__ int s[256];
    int t = threadIdx.x;
    int v = (t < SCAN_B) ? g_bsum[t] : 0;
    s[t] = v;
    __syncthreads();
    for (int off = 1; off < 256; off <<= 1) {
        int u = (t >= off) ? s[t - off] : 0;
        __syncthreads();
        s[t] += u;
        __syncthreads();
    }
    g_boff[t] = s[t] - v;
    if (t == 255) g_row_ptr[N_NODES] = s[255];
}

__global__ __launch_bounds__(256) void scan3_kernel() {
    __shared__ int s[256];
    int t = threadIdx.x;
    int i = blockIdx.x * 256 + t;
    int v = (i < N_NODES) ? g_deg_in_i[i] : 0;
    s[t] = v;
    __syncthreads();
    for (int off = 1; off < 256; off <<= 1) {
        int u = (t >= off) ? s[t - off] : 0;
        __syncthreads();
        s[t] += u;
        __syncthreads();
    }
    if (i < N_NODES) g_row_ptr[i] = g_boff[blockIdx.x] + s[t] - v;
}

__global__ void fill_kernel(const int* __restrict__ src, const int* __restrict__ dst) {
    int e = blockIdx.x * blockDim.x + threadIdx.x;
    if (e < N_EDGES) {
        int d = dst[e];
        int s = src[e];
        int pos = g_row_ptr[d] + atomicAdd(&g_cursor[d], 1);
        g_edge[pos] = make_int2(s, __float_as_int(g_ns[s]));
    }
}

// ---------------- W1 -> transposed bf16 hi/lo split ----------------
__global__ void w1split_kernel(const float* __restrict__ W1) {
    int i = blockIdx.x * 256 + threadIdx.x;     // over 512*128
    if (i < IN_F * NH) {
        int k = i >> 7, n = i & 127;
        float w = W1[i];
        uint16_t hb = bf16r(w);
        float hf = __uint_as_float((uint32_t)hb << 16);
        uint16_t lb = bf16r(w - hf);
        g_w1t_hi[n * IN_F + k] = hb;
        g_w1t_lo[n * IN_F + k] = lb;
    }
}

// ---------------- GEMM1: h1 = X @ W1 via mma.sync bf16 3-term split --------
#define G1M_STAGE 32768
#define G1M_SMEM  (2 * G1M_STAGE)

__global__ __launch_bounds__(256) void gemm1_mma_kernel(const float* __restrict__ X) {
    extern __shared__ char smem[];
    const uint32_t sb = smem_to_u32(smem);
    const int tid  = threadIdx.x;
    const int lane = tid & 31;
    const int wid  = tid >> 5;
    const int bm   = blockIdx.x * 128;
    const int mw   = (wid & 3) * 32;     // warp M offset
    const int nw   = (wid >> 2) * 64;    // warp N offset

    float acc[2][8][4];
    #pragma unroll
    for (int i = 0; i < 2; i++)
        #pragma unroll
        for (int j = 0; j < 8; j++)
            #pragma unroll
            for (int q = 0; q < 4; q++) acc[i][j][q] = 0.f;

    const int lrow  = tid >> 1;
    const int lhalf = tid & 1;
    const int lsw   = (lrow >> 1) & 3;

    auto load_stage = [&](int st, int k0) {
        char* stg = smem + st * G1M_STAGE;
        {
            const int gr = bm + lrow;
            const bool ok = gr < N_NODES;
            const float* xp = &X[(size_t)gr * IN_F + k0 + lhalf * 16];
            #pragma unroll
            for (int q = 0; q < 4; q++) {
                float4 v = ok ? *reinterpret_cast<const float4*>(xp + q * 4)
                              : make_float4(0.f, 0.f, 0.f, 0.f);
                uint32_t h0 = packbf(v.x, v.y);
                uint32_t h1 = packbf(v.z, v.w);
                float l0 = v.x - __uint_as_float(h0 << 16);
                float l1 = v.y - __uint_as_float(h0 & 0xffff0000u);
                float l2 = v.z - __uint_as_float(h1 << 16);
                float l3 = v.w - __uint_as_float(h1 & 0xffff0000u);
                uint32_t p0 = packbf(l0, l1);
                uint32_t p1 = packbf(l2, l3);
                int c16 = lhalf * 2 + (q >> 1);
                uint32_t off = (uint32_t)(lrow * 64 + ((c16 ^ lsw) * 16) + (q & 1) * 8);
                *reinterpret_cast<uint2*>(stg + off)        = make_uint2(h0, h1);
                *reinterpret_cast<uint2*>(stg + 8192 + off) = make_uint2(p0, p1);
            }
        }
        {
            const uint16_t* bh = &g_w1t_hi[lrow * IN_F + k0 + lhalf * 16];
            const uint16_t* bl = &g_w1t_lo[lrow * IN_F + k0 + lhalf * 16];
            #pragma unroll
            for (int q = 0; q < 2; q++) {
                uint4 hv = *reinterpret_cast<const uint4*>(bh + q * 8);
                uint4 lv = *reinterpret_cast<const uint4*>(bl + q * 8);
                int c16 = lhalf * 2 + q;
                uint32_t off = (uint32_t)(lrow * 64 + ((c16 ^ lsw) * 16));
                *reinterpret_cast<uint4*>(stg + 16384 + off) = hv;
                *reinterpret_cast<uint4*>(stg + 24576 + off) = lv;
            }
        }
    };

    load_stage(0, 0);
    __syncthreads();

    const int a_rlane = lane & 15;
    const int a_kg    = lane >> 4;
    const int b_grp   = lane >> 3;
    const int b_rlane = (b_grp >> 1) * 8 + (lane & 7);
    const int b_kg    = b_grp & 1;

    const int NCHUNK = IN_F / 32;           // 16
    for (int c = 0; c < NCHUNK; c++) {
        const int cur = c & 1;
        if (c + 1 < NCHUNK) load_stage(cur ^ 1, (c + 1) * 32);

        const uint32_t sbase = sb + cur * G1M_STAGE;
        #pragma unroll
        for (int ks = 0; ks < 2; ks++) {
            uint32_t Ahi[2][4], Alo[2][4];
            #pragma unroll
            for (int mt = 0; mt < 2; mt++) {
                int row = mw + mt * 16 + a_rlane;
                uint32_t byteoff = (uint32_t)(row * 64 +
                    (((ks * 2 + a_kg) ^ ((row >> 1) & 3)) * 16));
                ldmx4(Ahi[mt], sbase + byteoff);
                ldmx4(Alo[mt], sbase + 8192 + byteoff);
            }
            uint32_t Bhi[8][2], Blo[8][2];
            #pragma unroll
            for (int ntp = 0; ntp < 4; ntp++) {
                int n = nw + ntp * 16 + b_rlane;
                uint32_t byteoff = (uint32_t)(n * 64 +
                    (((ks * 2 + b_kg) ^ ((n >> 1) & 3)) * 16));
                uint32_t rh[4], rl[4];
                ldmx4(rh, sbase + 16384 + byteoff);
                ldmx4(rl, sbase + 24576 + byteoff);
                Bhi[ntp * 2][0] = rh[0]; Bhi[ntp * 2][1] = rh[1];
                Bhi[ntp * 2 + 1][0] = rh[2]; Bhi[ntp * 2 + 1][1] = rh[3];
                Blo[ntp * 2][0] = rl[0]; Blo[ntp * 2][1] = rl[1];
                Blo[ntp * 2 + 1][0] = rl[2]; Blo[ntp * 2 + 1][1] = rl[3];
            }
            #pragma unroll
            for (int mt = 0; mt < 2; mt++)
                #pragma unroll
                for (int nt = 0; nt < 8; nt++)
                    mma_bf16(acc[mt][nt], Ahi[mt], Bhi[nt]);
            #pragma unroll
            for (int mt = 0; mt < 2; mt++)
                #pragma unroll
                for (int nt = 0; nt < 8; nt++)
                    mma_bf16(acc[mt][nt], Alo[mt], Bhi[nt]);
            #pragma unroll
            for (int mt = 0; mt < 2; mt++)
                #pragma unroll
                for (int nt = 0; nt < 8; nt++)
                    mma_bf16(acc[mt][nt], Ahi[mt], Blo[nt]);
        }
        __syncthreads();
    }

    // epilogue: convert to fp16 and store half2 per 2 cols
    #pragma unroll
    for (int mt = 0; mt < 2; mt++) {
        int row = bm + mw + mt * 16 + (lane >> 2);
        #pragma unroll
        for (int nt = 0; nt < 8; nt++) {
            int col = nw + nt * 8 + (lane & 3) * 2;
            __half2 p0 = __floats2half2_rn(acc[mt][nt][0], acc[mt][nt][1]);
            __half2 p1 = __floats2half2_rn(acc[mt][nt][2], acc[mt][nt][3]);
            if (row < N_NODES)
                *reinterpret_cast<__half2*>(&g_h1[(size_t)row * NH + col]) = p0;
            if (row + 8 < N_NODES)
                *reinterpret_cast<__half2*>(&g_h1[(size_t)(row + 8) * NH + col]) = p1;
        }
    }
}

// ---------------- agg1 over [base, base+count): fp16 gather, fp32 accum ----
__global__ void agg1_kernel(const float* __restrict__ b1, int base, int count) {
    int t = blockIdx.x * blockDim.x + threadIdx.x;
    int w = (t >> 5);
    int lane = t & 31;
    if (w >= count) return;
    w += base;
    int beg = g_row_ptr[w], end = g_row_ptr[w + 1];

    unsigned long long a01 = 0ull, a23 = 0ull;
    for (int j = beg; j < end; j += 32) {
        int n = end - j; if (n > 32) n = 32;
        int2 ed = (j + lane < end) ? g_edge[j + lane] : make_int2(0, 0);
        #pragma unroll 8
        for (int i = 0; i < n; i++) {
            int   s = __shfl_sync(0xffffffffu, ed.x, i);
            float f = __int_as_float(__shfl_sync(0xffffffffu, ed.y, i));
            uint2 v = __ldg(reinterpret_cast<const uint2*>(&g_h1[(size_t)s * NH]) + lane);
            float2 f0 = __half22float2(*reinterpret_cast<__half2*>(&v.x));
            float2 f1 = __half22float2(*reinterpret_cast<__half2*>(&v.y));
            unsigned long long pf = pack2(f);
            fma2(a01, pf, packf2(f0.x, f0.y));
            fma2(a23, pf, packf2(f1.x, f1.y));
        }
    }
    float nd = g_nd[w];
    float4 bb = __ldg(reinterpret_cast<const float4*>(b1) + lane);
    float2 p01 = unpack2(a01);
    float2 p23 = unpack2(a23);
    float4 r;
    r.x = fmaxf(p01.x * nd + bb.x, 0.f);
    r.y = fmaxf(p01.y * nd + bb.y, 0.f);
    r.z = fmaxf(p23.x * nd + bb.z, 0.f);
    r.w = fmaxf(p23.y * nd + bb.w, 0.f);
    *(reinterpret_cast<float4*>(&g_x2[(size_t)w * NH]) + lane) = r;
}

// ---------------- GEMM2 over [base, base+count) -----------------------------
__global__ __launch_bounds__(256) void gemm2_kernel(const float* __restrict__ W2,
                                                    int base, int count) {
    __shared__ float W2s[NH * NC];
    __shared__ float xs[8][NH];

    int tid = threadIdx.x;
    for (int i = tid; i < NH * NC; i += 256) W2s[i] = W2[i];
    __syncthreads();

    const int n_tiles = (count + 7) / 8;
    for (int tile = blockIdx.x; tile < n_tiles; tile += gridDim.x) {
        int row0 = base + tile * 8;
        int lim  = base + count;
        #pragma unroll
        for (int i = 0; i < 4; i++) {
            int j = tid + i * 256;
            int r = j >> 7, k = j & 127;
            int row = row0 + r;
            xs[r][k] = (row < lim) ? g_x2[(size_t)row * NH + k] : 0.f;
        }
        __syncthreads();

        if (tid < 8 * (NC / 2)) {
            int r  = tid / (NC / 2);
            int cp = tid % (NC / 2);
            int row = row0 + r;
            if (row < lim) {
                unsigned long long acc = 0ull;
                const unsigned long long* wp =
                    reinterpret_cast<const unsigned long long*>(W2s) + cp;
                #pragma unroll 8
                for (int k = 0; k < NH; k++)
                    fma2(acc, pack2(xs[r][k]), wp[k * (NC / 2)]);
                float2 p = unpack2(acc);
                *reinterpret_cast<float2*>(&g_h2[(size_t)row * NC + cp * 2]) = p;
            }
        }
        __syncthreads();
    }
}

// ---------------- agg2: out[n] = nd[n]*sum ns[s]*h2[s] + b2 -----------------
__global__ void agg2_kernel(const float* __restrict__ b2, float* __restrict__ out) {
    int t = blockIdx.x * blockDim.x + threadIdx.x;
    int w = t >> 5, lane = t & 31;
    if (w >= N_NODES) return;
    int beg = g_row_ptr[w], end = g_row_ptr[w + 1];

    float acc0 = 0.f, acc1 = 0.f;
    for (int j = beg; j < end; j += 32) {
        int n = end - j; if (n > 32) n = 32;
        int2 ed = (j + lane < end) ? g_edge[j + lane] : make_int2(0, 0);
        #pragma unroll 8
        for (int i = 0; i < n; i++) {
            int   s = __shfl_sync(0xffffffffu, ed.x, i);
            float f = __int_as_float(__shfl_sync(0xffffffffu, ed.y, i));
            const float* row = &g_h2[(size_t)s * NC];
            acc0 = fmaf(f, __ldg(row + lane), acc0);
            if (lane < 8) acc1 = fmaf(f, __ldg(row + 32 + lane), acc1);
        }
    }
    float nd = g_nd[w];
    out[(size_t)w * NC + lane] = acc0 * nd + __ldg(b2 + lane);
    if (lane < 8)
        out[(size_t)w * NC + 32 + lane] = acc1 * nd + __ldg(b2 + 32 + lane);
}

// ---------------- launch ----------------
extern "C" void kernel_launch(void* const* d_in, const int* in_sizes, int n_in,
                              void* d_out, int out_size) {
    const float* X   = (const float*)d_in[0];
    const float* W1  = (const float*)d_in[1];
    const float* b1  = (const float*)d_in[2];
    const float* W2  = (const float*)d_in[3];
    const float* b2  = (const float*)d_in[4];
    const int*   src = (const int*)  d_in[5];
    const int*   dst = (const int*)  d_in[6];
    float* out = (float*)d_out;

    static cudaStream_t s_side = nullptr;
    static cudaEvent_t  ev_fork = nullptr, ev_join = nullptr;
    static cudaEvent_t  ev_a = nullptr, ev_g2a = nullptr;
    if (s_side == nullptr) {
        cudaStreamCreateWithFlags(&s_side, cudaStreamNonBlocking);
        cudaEventCreateWithFlags(&ev_fork, cudaEventDisableTiming);
        cudaEventCreateWithFlags(&ev_join, cudaEventDisableTiming);
        cudaEventCreateWithFlags(&ev_a, cudaEventDisableTiming);
        cudaEventCreateWithFlags(&ev_g2a, cudaEventDisableTiming);
        cudaFuncSetAttribute(gemm1_mma_kernel,
                             cudaFuncAttributeMaxDynamicSharedMemorySize, G1M_SMEM);
    }

    // fork: side stream runs the graph-prep chain
    cudaEventRecord(ev_fork, 0);
    cudaStreamWaitEvent(s_side, ev_fork, 0);

    zero_kernel<<<256, 256, 0, s_side>>>();
    deg_kernel<<<(N_EDGES + 255) / 256, 256, 0, s_side>>>(src, dst);
    norm_kernel<<<(N_NODES + 255) / 256, 256, 0, s_side>>>();
    scan1_kernel<<<SCAN_B, 256, 0, s_side>>>();
    scan2_kernel<<<1, 256, 0, s_side>>>();
    scan3_kernel<<<SCAN_B, 256, 0, s_side>>>();
    fill_kernel<<<(N_EDGES + 255) / 256, 256, 0, s_side>>>(src, dst);

    // main stream: W1 split + tensor-core GEMM1
    w1split_kernel<<<(IN_F * NH + 255) / 256, 256>>>(W1);
    gemm1_mma_kernel<<<(N_NODES + 127) / 128, 256, G1M_SMEM>>>(X);

    // join
    cudaEventRecord(ev_join, s_side);
    cudaStreamWaitEvent(0, ev_join, 0);

    // agg1 half A; gemm2(A) overlaps agg1 half B
    agg1_kernel<<<(N_HALF * 32 + 255) / 256, 256>>>(b1, 0, N_HALF);
    cudaEventRecord(ev_a, 0);
    cudaStreamWaitEvent(s_side, ev_a, 0);
    gemm2_kernel<<<1024, 256, 0, s_side>>>(W2, 0, N_HALF);

    agg1_kernel<<<((N_NODES - N_HALF) * 32 + 255) / 256, 256>>>(b1, N_HALF, N_NODES - N_HALF);
    gemm2_kernel<<<1024, 256>>>(W2, N_HALF, N_NODES - N_HALF);

    cudaEventRecord(ev_g2a, s_side);
    cudaStreamWaitEvent(0, ev_g2a, 0);

    agg2_kernel<<<(N_NODES * 32 + 255) / 256, 256>>>(b2, out);
}